// round 8
// baseline (speedup 1.0000x reference)
#include <cuda_runtime.h>
#include <cstdint>

// Problem constants
#define B_   16
#define N_   2048
#define F_   64
#define HD_  256
#define K_   128
#define G_   18
#define FUSE_ 274

// Scratch (allocation-free rule: __device__ globals)
__device__ float g_buf1[B_ * N_ * HD_];
__device__ float g_buf2[B_ * N_ * HD_];
__device__ float g_colsum[B_ * HD_];
__device__ float g_bufX[B_ * N_ * F_];
__device__ float g_bufW1[F_ * HD_];
__device__ float g_bufW2[HD_ * HD_];

// Epilogue modes
#define EPI_LN_STORE  1
#define EPI_LN_COLSUM 2

// ---------------------------------------------------------------------------
__device__ __forceinline__ uint32_t smem_u32(const void* p) {
    uint32_t a;
    asm("{ .reg .u64 t; cvta.to.shared.u64 t, %1; cvt.u32.u64 %0, t; }"
        : "=r"(a) : "l"(p));
    return a;
}

__device__ __forceinline__ void cp16(uint32_t dst, const void* src) {
    asm volatile("cp.async.cg.shared.global [%0], [%1], 16;"
                 :: "r"(dst), "l"(src) : "memory");
}
#define CP_COMMIT() asm volatile("cp.async.commit_group;" ::: "memory")
#define CP_WAIT(n)  asm volatile("cp.async.wait_group %0;" :: "n"(n) : "memory")

__device__ __forceinline__ float rna_tf32(float f) {
    uint32_t u;
    asm("cvt.rna.tf32.f32 %0, %1;" : "=r"(u) : "f"(f));
    return __uint_as_float(u);
}

__device__ __forceinline__ void mma_tf32(float* c, const uint32_t* a, const uint32_t* b) {
    asm volatile(
        "mma.sync.aligned.m16n8k8.row.col.f32.tf32.tf32.f32 "
        "{%0,%1,%2,%3}, {%4,%5,%6,%7}, {%8,%9}, {%0,%1,%2,%3};"
        : "+f"(c[0]), "+f"(c[1]), "+f"(c[2]), "+f"(c[3])
        : "r"(a[0]), "r"(a[1]), "r"(a[2]), "r"(a[3]), "r"(b[0]), "r"(b[1]));
}

// ---------------------------------------------------------------------------
__global__ __launch_bounds__(256)
void round_tf32_kernel(const float* __restrict__ in, float* __restrict__ out, int n4) {
    int i = blockIdx.x * blockDim.x + threadIdx.x;
    if (i < n4) {
        float4 v = reinterpret_cast<const float4*>(in)[i];
        v.x = rna_tf32(v.x); v.y = rna_tf32(v.y);
        v.z = rna_tf32(v.z); v.w = rna_tf32(v.w);
        reinterpret_cast<float4*>(out)[i] = v;
    }
}

// ---------------------------------------------------------------------------
// TF32 mma.sync GEMM, plain store epilogue (rna-rounded).
// BM/BN/threads/warp-grid/stages/min-blocks templated. C[bz] = A[bz] @ Bm[bz]
// ---------------------------------------------------------------------------
template <int BM, int BN, int NT, int WROWS, int WCOLS, int S, int MINB>
__global__ __launch_bounds__(NT, MINB)
void tf32_gemm_store(const float* __restrict__ A, const float* __restrict__ Bm,
                     float* __restrict__ C, int Kd, int Ncols,
                     long long sA, long long sB, long long sC) {
    constexpr int BK = 32;
    constexpr int WM = BM / WROWS, WN = BN / WCOLS;
    constexpr int MF = WM / 16, NF = WN / 8;
    constexpr int AP = 36;          // A smem pitch: conflict-free frag reads
    constexpr int BP = BN + 8;      // B smem pitch
    constexpr int AS_F = BM * AP;
    constexpr int BS_F = BK * BP;
    constexpr int ST_F = AS_F + BS_F;

    extern __shared__ float smem[];
    const uint32_t sbase = smem_u32(smem);

    const int tid = threadIdx.x, lane = tid & 31, wid = tid >> 5;
    const int wm = (wid / WCOLS) * WM, wn = (wid % WCOLS) * WN;

    const long long bz = blockIdx.z;
    const float* Ab = A + bz * sA + (long long)blockIdx.y * BM * Kd;
    const float* Bb = Bm + bz * sB + blockIdx.x * BN;
    float*       Cb = C + bz * sC + (long long)blockIdx.y * BM * Ncols
                        + blockIdx.x * BN;

    float acc[MF][NF][4];
#pragma unroll
    for (int i = 0; i < MF; i++)
#pragma unroll
        for (int j = 0; j < NF; j++)
#pragma unroll
            for (int r = 0; r < 4; r++) acc[i][j][r] = 0.f;

    const int nch = Kd >> 5;

    auto load_stage = [&](int s, int kc) {
        const float* Ak = Ab + kc * BK;
        constexpr int AI = BM * 8 / NT;     // float4s per thread for A
#pragma unroll
        for (int i = 0; i < AI; i++) {
            int idx = tid + i * NT;
            int r = idx >> 3, c4 = idx & 7;
            cp16(sbase + (uint32_t)(s * ST_F + r * AP + c4 * 4) * 4u,
                 Ak + (long long)r * Kd + c4 * 4);
        }
        const float* Bk = Bb + (long long)(kc * BK) * Ncols;
        constexpr int BI = (BN * BK) / (4 * NT);
        constexpr int C4 = BN / 4;
#pragma unroll
        for (int i = 0; i < BI; i++) {
            int idx = tid + i * NT;
            int r = idx / C4, c4 = idx % C4;
            cp16(sbase + (uint32_t)(s * ST_F + AS_F + r * BP + c4 * 4) * 4u,
                 Bk + (long long)r * Ncols + c4 * 4);
        }
    };

    auto compute_stage = [&](int s) {
        const uint32_t* As = reinterpret_cast<const uint32_t*>(smem + s * ST_F);
        const uint32_t* Bs = reinterpret_cast<const uint32_t*>(smem + s * ST_F + AS_F);
#pragma unroll
        for (int kk = 0; kk < 4; kk++) {
            const int k0 = kk * 8;
            uint32_t af[MF][4], bfr[NF][2];
#pragma unroll
            for (int mf = 0; mf < MF; mf++) {
                int m = wm + mf * 16 + (lane >> 2);
                int k = k0 + (lane & 3);
                af[mf][0] = As[m * AP + k];
                af[mf][1] = As[(m + 8) * AP + k];
                af[mf][2] = As[m * AP + k + 4];
                af[mf][3] = As[(m + 8) * AP + k + 4];
            }
#pragma unroll
            for (int nf = 0; nf < NF; nf++) {
                int n = wn + nf * 8 + (lane >> 2);
                int k = k0 + (lane & 3);
                bfr[nf][0] = Bs[k * BP + n];
                bfr[nf][1] = Bs[(k + 4) * BP + n];
            }
#pragma unroll
            for (int mf = 0; mf < MF; mf++)
#pragma unroll
                for (int nf = 0; nf < NF; nf++)
                    mma_tf32(acc[mf][nf], af[mf], bfr[nf]);
        }
    };

#pragma unroll
    for (int s = 0; s < S - 1; s++) {
        if (s < nch) load_stage(s, s);
        CP_COMMIT();
    }
    for (int kc = 0; kc < nch; kc++) {
        CP_WAIT(S - 2);
        __syncthreads();
        if (kc + S - 1 < nch) load_stage((kc + S - 1) % S, kc + S - 1);
        CP_COMMIT();
        compute_stage(kc % S);
        __syncthreads();
    }

#pragma unroll
    for (int mf = 0; mf < MF; mf++) {
#pragma unroll
        for (int nf = 0; nf < NF; nf++) {
            int row = wm + mf * 16 + (lane >> 2);
            int col = wn + nf * 8 + (lane & 3) * 2;
            float2 v0 = make_float2(rna_tf32(acc[mf][nf][0]),
                                    rna_tf32(acc[mf][nf][1]));
            float2 v1 = make_float2(rna_tf32(acc[mf][nf][2]),
                                    rna_tf32(acc[mf][nf][3]));
            *reinterpret_cast<float2*>(Cb + (long long)row * Ncols + col) = v0;
            *reinterpret_cast<float2*>(Cb + (long long)(row + 8) * Ncols + col) = v1;
        }
    }
}

// ---------------------------------------------------------------------------
// TF32 GEMM + fused bias/LN/ReLU epilogue (BN == Ncols == 256), as in R5.
// EPI_LN_STORE: rna-rounded store. EPI_LN_COLSUM: per-batch column sums only.
// ---------------------------------------------------------------------------
template <int EPI>
__global__ __launch_bounds__(256)
void tf32_ln_gemm(const float* __restrict__ A, const float* __restrict__ Bm,
                  float* __restrict__ C, int Kd,
                  const float* __restrict__ bias,
                  const float* __restrict__ gamma,
                  const float* __restrict__ beta,
                  float* __restrict__ colsum) {
    constexpr int BM = 128, BK = 32, BN = 256, S = 2;
    constexpr int WROWS = 2, WCOLS = 4;
    constexpr int WM = BM / WROWS, WN = BN / WCOLS;
    constexpr int MF = WM / 16, NF = WN / 8;
    constexpr int AP = 36, BP = BN + 8;
    constexpr int AS_F = BM * AP, BS_F = BK * BP;
    constexpr int ST_F = AS_F + BS_F;
    constexpr int EP = 260;

    extern __shared__ float smem[];
    const uint32_t sbase = smem_u32(smem);

    const int tid = threadIdx.x, lane = tid & 31, wid = tid >> 5;
    const int wm = (wid / WCOLS) * WM, wn = (wid % WCOLS) * WN;

    const float* Ab = A + (long long)blockIdx.y * BM * Kd;

    float acc[MF][NF][4];
#pragma unroll
    for (int i = 0; i < MF; i++)
#pragma unroll
        for (int j = 0; j < NF; j++)
#pragma unroll
            for (int r = 0; r < 4; r++) acc[i][j][r] = 0.f;

    const int nch = Kd >> 5;

    auto load_stage = [&](int s, int kc) {
        const float* Ak = Ab + kc * BK;
#pragma unroll
        for (int i = 0; i < 4; i++) {
            int idx = tid + i * 256;
            int r = idx >> 3, c4 = idx & 7;
            cp16(sbase + (uint32_t)(s * ST_F + r * AP + c4 * 4) * 4u,
                 Ak + (long long)r * Kd + c4 * 4);
        }
        const float* Bk = Bm + (long long)(kc * BK) * BN;
#pragma unroll
        for (int i = 0; i < 8; i++) {
            int idx = tid + i * 256;
            int r = idx >> 6, c4 = idx & 63;
            cp16(sbase + (uint32_t)(s * ST_F + AS_F + r * BP + c4 * 4) * 4u,
                 Bk + (long long)r * BN + c4 * 4);
        }
    };

    auto compute_stage = [&](int s) {
        const uint32_t* As = reinterpret_cast<const uint32_t*>(smem + s * ST_F);
        const uint32_t* Bs = reinterpret_cast<const uint32_t*>(smem + s * ST_F + AS_F);
#pragma unroll
        for (int kk = 0; kk < 4; kk++) {
            const int k0 = kk * 8;
            uint32_t af[MF][4], bfr[NF][2];
#pragma unroll
            for (int mf = 0; mf < MF; mf++) {
                int m = wm + mf * 16 + (lane >> 2);
                int k = k0 + (lane & 3);
                af[mf][0] = As[m * AP + k];
                af[mf][1] = As[(m + 8) * AP + k];
                af[mf][2] = As[m * AP + k + 4];
                af[mf][3] = As[(m + 8) * AP + k + 4];
            }
#pragma unroll
            for (int nf = 0; nf < NF; nf++) {
                int n = wn + nf * 8 + (lane >> 2);
                int k = k0 + (lane & 3);
                bfr[nf][0] = Bs[k * BP + n];
                bfr[nf][1] = Bs[(k + 4) * BP + n];
            }
#pragma unroll
            for (int mf = 0; mf < MF; mf++)
#pragma unroll
                for (int nf = 0; nf < NF; nf++)
                    mma_tf32(acc[mf][nf], af[mf], bfr[nf]);
        }
    };

#pragma unroll
    for (int s = 0; s < S - 1; s++) {
        if (s < nch) load_stage(s, s);
        CP_COMMIT();
    }
    for (int kc = 0; kc < nch; kc++) {
        CP_WAIT(S - 2);
        __syncthreads();
        if (kc + S - 1 < nch) load_stage((kc + S - 1) % S, kc + S - 1);
        CP_COMMIT();
        compute_stage(kc % S);
        __syncthreads();
    }

    // stash accumulators into smem tile [128][EP]
    __syncthreads();
#pragma unroll
    for (int mf = 0; mf < MF; mf++) {
#pragma unroll
        for (int nf = 0; nf < NF; nf++) {
            int row = wm + mf * 16 + (lane >> 2);
            int col = wn + nf * 8 + (lane & 3) * 2;
            smem[row * EP + col]     = acc[mf][nf][0];
            smem[row * EP + col + 1] = acc[mf][nf][1];
            smem[(row + 8) * EP + col]     = acc[mf][nf][2];
            smem[(row + 8) * EP + col + 1] = acc[mf][nf][3];
        }
    }
    __syncthreads();

    float rb[8], rg[8], rt[8];
#pragma unroll
    for (int j = 0; j < 8; j++) {
        rb[j] = __ldg(&bias[lane * 8 + j]);
        rg[j] = __ldg(&gamma[lane * 8 + j]);
        rt[j] = __ldg(&beta[lane * 8 + j]);
    }

    const float inv = 1.f / (float)HD_;
#pragma unroll 1
    for (int rr = 0; rr < 16; rr++) {
        const int r = wid * 16 + rr;
        float x[8];
        float4 v0 = *reinterpret_cast<float4*>(&smem[r * EP + lane * 8]);
        float4 v1 = *reinterpret_cast<float4*>(&smem[r * EP + lane * 8 + 4]);
        x[0] = v0.x; x[1] = v0.y; x[2] = v0.z; x[3] = v0.w;
        x[4] = v1.x; x[5] = v1.y; x[6] = v1.z; x[7] = v1.w;
        float s = 0.f, s2 = 0.f;
#pragma unroll
        for (int j = 0; j < 8; j++) {
            x[j] += rb[j];
            s += x[j]; s2 += x[j] * x[j];
        }
#pragma unroll
        for (int o = 16; o; o >>= 1) {
            s  += __shfl_xor_sync(0xFFFFFFFFu, s, o);
            s2 += __shfl_xor_sync(0xFFFFFFFFu, s2, o);
        }
        float mu = s * inv;
        float rstd = rsqrtf(s2 * inv - mu * mu + 1e-5f);
        float y[8];
#pragma unroll
        for (int j = 0; j < 8; j++) {
            float v = (x[j] - mu) * rstd * rg[j] + rt[j];
            y[j] = fmaxf(v, 0.f);
        }
        if (EPI == EPI_LN_STORE) {
#pragma unroll
            for (int j = 0; j < 8; j++) y[j] = rna_tf32(y[j]);
            float* crow = C + (long long)blockIdx.y * BM * BN
                            + (long long)r * BN + lane * 8;
            *reinterpret_cast<float4*>(crow)     = make_float4(y[0], y[1], y[2], y[3]);
            *reinterpret_cast<float4*>(crow + 4) = make_float4(y[4], y[5], y[6], y[7]);
        } else {
            *reinterpret_cast<float4*>(&smem[r * EP + lane * 8]) =
                make_float4(y[0], y[1], y[2], y[3]);
            *reinterpret_cast<float4*>(&smem[r * EP + lane * 8 + 4]) =
                make_float4(y[4], y[5], y[6], y[7]);
        }
    }

    if (EPI == EPI_LN_COLSUM) {
        __syncthreads();
        float s = 0.f;
#pragma unroll 8
        for (int r = 0; r < BM; r++) s += smem[r * EP + tid];
        const int b = (int)(blockIdx.y >> 4);
        atomicAdd(&colsum[b * HD_ + tid], s);
    }
}

// ---------------------------------------------------------------------------
__global__ __launch_bounds__(256)
void head_kernel(const float* __restrict__ colsum, const float* __restrict__ gvec,
                 const float* __restrict__ Ws, const float* __restrict__ bs,
                 const float* __restrict__ Wa, const float* __restrict__ ba,
                 float* __restrict__ out) {
    int b = blockIdx.x, t = threadIdx.x;
    __shared__ float fused[FUSE_];
    fused[t] = colsum[b * HD_ + t] * (1.f / (float)N_);
    if (t < G_) fused[HD_ + t] = gvec[b * G_ + t];
    __syncthreads();

    if (t < K_) {
        float acc = ba[t];
#pragma unroll 4
        for (int i = 0; i < FUSE_; i++) acc += fused[i] * Wa[i * K_ + t];
        out[B_ + b * K_ + t] = acc;
    } else if (t == K_) {
        float acc = bs[0];
        for (int i = 0; i < FUSE_; i++) acc += fused[i] * Ws[i];
        out[b] = acc;
    }
}

// ---------------------------------------------------------------------------
extern "C" void kernel_launch(void* const* d_in, const int* in_sizes, int n_in,
                              void* d_out, int out_size) {
    const float* A_hat = (const float*)d_in[0];
    const float* X     = (const float*)d_in[1];
    const float* gvec  = (const float*)d_in[2];
    const float* W1    = (const float*)d_in[3];
    const float* b1    = (const float*)d_in[4];
    const float* g1    = (const float*)d_in[5];
    const float* be1   = (const float*)d_in[6];
    const float* W2    = (const float*)d_in[7];
    const float* b2    = (const float*)d_in[8];
    const float* g2    = (const float*)d_in[9];
    const float* be2   = (const float*)d_in[10];
    const float* Ws    = (const float*)d_in[11];
    const float* bs    = (const float*)d_in[12];
    const float* Wa    = (const float*)d_in[13];
    const float* ba    = (const float*)d_in[14];
    float* out = (float*)d_out;

    float *buf1, *buf2, *csum, *bX, *bW1, *bW2;
    cudaGetSymbolAddress((void**)&buf1, g_buf1);
    cudaGetSymbolAddress((void**)&buf2, g_buf2);
    cudaGetSymbolAddress((void**)&csum, g_colsum);
    cudaGetSymbolAddress((void**)&bX,  g_bufX);
    cudaGetSymbolAddress((void**)&bW1, g_bufW1);
    cudaGetSymbolAddress((void**)&bW2, g_bufW2);

    // K1: BM=64, BN=64, 128 thr, S=3.  ST_F = 64*36 + 32*72 = 4608 fl
    constexpr int SMEM_K1 = 3 * 4608 * 4;   // 55296
    // K3: BM=128, BN=64, 256 thr, S=2. ST_F = 128*36 + 32*72 = 6912 fl
    constexpr int SMEM_K3 = 2 * 6912 * 4;   // 55296
    // K2/K4: LN tile dominates
    constexpr int SMEM_LN = 128 * 260 * 4;  // 133120

    auto k1 = tf32_gemm_store<64, 64, 128, 2, 2, 3, 3>;
    auto k3 = tf32_gemm_store<128, 64, 256, 4, 2, 2, 2>;
    auto k2 = tf32_ln_gemm<EPI_LN_STORE>;
    auto k4 = tf32_ln_gemm<EPI_LN_COLSUM>;

    cudaFuncSetAttribute((const void*)k1, cudaFuncAttributeMaxDynamicSharedMemorySize, SMEM_K1);
    cudaFuncSetAttribute((const void*)k3, cudaFuncAttributeMaxDynamicSharedMemorySize, SMEM_K3);
    cudaFuncSetAttribute((const void*)k2, cudaFuncAttributeMaxDynamicSharedMemorySize, SMEM_LN);
    cudaFuncSetAttribute((const void*)k4, cudaFuncAttributeMaxDynamicSharedMemorySize, SMEM_LN);

    round_tf32_kernel<<<(B_ * N_ * F_ / 4 + 255) / 256, 256>>>(X,  bX,  B_ * N_ * F_ / 4);
    round_tf32_kernel<<<(F_ * HD_ / 4 + 255) / 256, 256>>>(W1, bW1, F_ * HD_ / 4);
    round_tf32_kernel<<<(HD_ * HD_ / 4 + 255) / 256, 256>>>(W2, bW2, HD_ * HD_ / 4);
    cudaMemsetAsync(csum, 0, B_ * HD_ * sizeof(float));

    // K1: T1 = A_hat @ X   (per batch 2048x2048 @ 2048x64) -> buf1 (rounded)
    k1<<<dim3(1, 32, 16), 128, SMEM_K1>>>(
        A_hat, bX, buf1, N_, F_,
        (long long)N_ * N_, (long long)N_ * F_, (long long)N_ * F_);
    // K2: H1 = relu(LN(T1@W1 + b1)) -> buf2 (rounded)
    k2<<<dim3(1, 256, 1), 256, SMEM_LN>>>(
        buf1, bW1, buf2, F_, b1, g1, be1, nullptr);
    // K3: T2 = A_hat @ H1  (per batch 2048x2048 @ 2048x256) -> buf1 (rounded)
    k3<<<dim3(4, 16, 16), 256, SMEM_K3>>>(
        A_hat, buf2, buf1, N_, HD_,
        (long long)N_ * N_, (long long)N_ * HD_, (long long)N_ * HD_);
    // K4: colsum += colsums(relu(LN(T2@W2 + b2)))
    k4<<<dim3(1, 256, 1), 256, SMEM_LN>>>(
        buf1, bW2, nullptr, HD_, b2, g2, be2, csum);
    // K5: mean + concat + heads -> out
    head_kernel<<<B_, 256>>>(csum, gvec, Ws, bs, Wa, ba, out);
}

// round 9
// speedup vs baseline: 1.2487x; 1.2487x over previous
#include <cuda_runtime.h>
#include <cuda_fp16.h>
#include <cstdint>

// Problem constants
#define B_   16
#define N_   2048
#define F_   64
#define HD_  256
#define K_   128
#define G_   18
#define FUSE_ 274

// Scratch (allocation-free rule: __device__ globals)
__device__ float g_buf1[B_ * N_ * HD_];          // T1 (32768x64 used) / T2
__device__ float g_buf2[B_ * N_ * HD_];
__device__ float g_colsum[B_ * HD_];
__device__ __half g_Ah[(size_t)B_ * N_ * N_];    // 134 MB fp16 A_hat
__device__ __half g_XT[B_ * F_ * N_];            // X^T fp16
__device__ __half g_H1T[B_ * HD_ * N_];          // H1^T fp16
__device__ float g_bufW1[F_ * HD_];
__device__ float g_bufW2[HD_ * HD_];

// Epilogue modes (tf32 LN kernel)
#define EPI_LN_TF16   1   // bias+LN+ReLU -> transposed fp16 store
#define EPI_LN_COLSUM 2   // bias+LN+ReLU -> column-sum atomics only

// ---------------------------------------------------------------------------
__device__ __forceinline__ uint32_t smem_u32(const void* p) {
    uint32_t a;
    asm("{ .reg .u64 t; cvta.to.shared.u64 t, %1; cvt.u32.u64 %0, t; }"
        : "=r"(a) : "l"(p));
    return a;
}

__device__ __forceinline__ void cp16(uint32_t dst, const void* src) {
    asm volatile("cp.async.cg.shared.global [%0], [%1], 16;"
                 :: "r"(dst), "l"(src) : "memory");
}
#define CP_COMMIT() asm volatile("cp.async.commit_group;" ::: "memory")
#define CP_WAIT(n)  asm volatile("cp.async.wait_group %0;" :: "n"(n) : "memory")

__device__ __forceinline__ float rna_tf32(float f) {
    uint32_t u;
    asm("cvt.rna.tf32.f32 %0, %1;" : "=r"(u) : "f"(f));
    return __uint_as_float(u);
}

__device__ __forceinline__ void mma_tf32(float* c, const uint32_t* a, const uint32_t* b) {
    asm volatile(
        "mma.sync.aligned.m16n8k8.row.col.f32.tf32.tf32.f32 "
        "{%0,%1,%2,%3}, {%4,%5,%6,%7}, {%8,%9}, {%0,%1,%2,%3};"
        : "+f"(c[0]), "+f"(c[1]), "+f"(c[2]), "+f"(c[3])
        : "r"(a[0]), "r"(a[1]), "r"(a[2]), "r"(a[3]), "r"(b[0]), "r"(b[1]));
}

__device__ __forceinline__ void mma_f16(float* c, const uint32_t* a, const uint32_t* b) {
    asm volatile(
        "mma.sync.aligned.m16n8k16.row.col.f32.f16.f16.f32 "
        "{%0,%1,%2,%3}, {%4,%5,%6,%7}, {%8,%9}, {%0,%1,%2,%3};"
        : "+f"(c[0]), "+f"(c[1]), "+f"(c[2]), "+f"(c[3])
        : "r"(a[0]), "r"(a[1]), "r"(a[2]), "r"(a[3]), "r"(b[0]), "r"(b[1]));
}

// ---------------------------------------------------------------------------
// fp32 -> fp16 stream convert (float4 in, uint2 out)
// ---------------------------------------------------------------------------
__global__ __launch_bounds__(256)
void convert_f16_kernel(const float* __restrict__ in,
                        __half* __restrict__ out, int n4) {
    int i = blockIdx.x * 256 + threadIdx.x;
    if (i < n4) {
        float4 v = reinterpret_cast<const float4*>(in)[i];
        __half2 lo = __float22half2_rn(make_float2(v.x, v.y));
        __half2 hi = __float22half2_rn(make_float2(v.z, v.w));
        uint2 p;
        p.x = *reinterpret_cast<uint32_t*>(&lo);
        p.y = *reinterpret_cast<uint32_t*>(&hi);
        reinterpret_cast<uint2*>(out)[i] = p;
    }
}

// ---------------------------------------------------------------------------
// X [b][2048][64] fp32 -> XT [b][64][2048] fp16
// ---------------------------------------------------------------------------
__global__ __launch_bounds__(256)
void transpose_x_kernel(const float* __restrict__ X, __half* __restrict__ XT) {
    __shared__ float t[32][33];
    int b = blockIdx.z, c0 = blockIdx.x * 32, r0 = blockIdx.y * 32;
    int tx = threadIdx.x & 31, ty = threadIdx.x >> 5;
    const float* Xb = X + (long long)b * N_ * F_;
#pragma unroll
    for (int i = 0; i < 4; i++)
        t[ty + i * 8][tx] = Xb[(long long)(r0 + ty + i * 8) * F_ + c0 + tx];
    __syncthreads();
    __half* XTb = XT + (long long)b * F_ * N_;
#pragma unroll
    for (int i = 0; i < 4; i++)
        XTb[(long long)(c0 + ty + i * 8) * N_ + r0 + tx] =
            __float2half_rn(t[tx][ty + i * 8]);
}

// ---------------------------------------------------------------------------
__global__ __launch_bounds__(256)
void round_tf32_kernel(const float* __restrict__ in, float* __restrict__ out, int n4) {
    int i = blockIdx.x * blockDim.x + threadIdx.x;
    if (i < n4) {
        float4 v = reinterpret_cast<const float4*>(in)[i];
        v.x = rna_tf32(v.x); v.y = rna_tf32(v.y);
        v.z = rna_tf32(v.z); v.w = rna_tf32(v.w);
        reinterpret_cast<float4*>(out)[i] = v;
    }
}

// ---------------------------------------------------------------------------
// FP16 mma.sync GEMM: C[bz] = A[bz] @ Bt[bz]^T   (fp32 accumulate)
// A [M][Kd] fp16 row-major, Bt [Ncols][Kd] fp16 row-major (pre-transposed B).
// BM=128, BK=32, 256 threads. Output fp32, rna-rounded.
// smem pitch 20 u32 (40 halves) -> conflict-free fragment reads.
// ---------------------------------------------------------------------------
template <int BN, int WROWS, int WCOLS, int S, int MINB>
__global__ __launch_bounds__(256, MINB)
void f16_mma_gemm(const __half* __restrict__ A,
                  const __half* __restrict__ Bt,
                  float* __restrict__ C, int Kd, int Ncols,
                  long long sA, long long sB, long long sC) {
    constexpr int BM = 128, BK = 32;
    constexpr int WM = BM / WROWS, WN = BN / WCOLS;
    constexpr int MF = WM / 16, NF = WN / 8;
    constexpr int APu = 20;              // u32 pitch
    constexpr int AS_U = BM * APu;
    constexpr int BS_U = BN * APu;
    constexpr int ST_U = AS_U + BS_U;

    extern __shared__ uint32_t smu[];
    const uint32_t sbase = smem_u32(smu);

    const int tid = threadIdx.x, lane = tid & 31, wid = tid >> 5;
    const int wm = (wid / WCOLS) * WM, wn = (wid % WCOLS) * WN;
    const long long bz = blockIdx.z;
    const __half* Ab  = A  + bz * sA + (long long)blockIdx.y * BM * Kd;
    const __half* Btb = Bt + bz * sB + (long long)blockIdx.x * BN * Kd;
    float* Cb = C + bz * sC + (long long)blockIdx.y * BM * Ncols + blockIdx.x * BN;

    float acc[MF][NF][4];
#pragma unroll
    for (int i = 0; i < MF; i++)
#pragma unroll
        for (int j = 0; j < NF; j++)
#pragma unroll
            for (int r = 0; r < 4; r++) acc[i][j][r] = 0.f;

    const int nch = Kd >> 5;

    auto load_stage = [&](int s, int kc) {
        const __half* Ak = Ab + kc * BK;
#pragma unroll
        for (int i = 0; i < 2; i++) {
            int idx = tid + i * 256;
            int r = idx >> 2, c8 = idx & 3;
            cp16(sbase + (uint32_t)(s * ST_U + r * APu + c8 * 4) * 4u,
                 Ak + (long long)r * Kd + c8 * 8);
        }
        const __half* Bk = Btb + kc * BK;
#pragma unroll
        for (int i = 0; i < BN / 64; i++) {
            int idx = tid + i * 256;
            int n = idx >> 2, c8 = idx & 3;
            cp16(sbase + (uint32_t)(s * ST_U + AS_U + n * APu + c8 * 4) * 4u,
                 Bk + (long long)n * Kd + c8 * 8);
        }
    };

    auto compute_stage = [&](int s) {
        const uint32_t* As = smu + s * ST_U;
        const uint32_t* Bs = smu + s * ST_U + AS_U;
#pragma unroll
        for (int ks = 0; ks < 2; ks++) {     // two K=16 steps per 32-k chunk
            const int kb = ks * 8 + (lane & 3);
            uint32_t af[MF][4], bfr[NF][2];
#pragma unroll
            for (int mf = 0; mf < MF; mf++) {
                int m = wm + mf * 16 + (lane >> 2);
                af[mf][0] = As[m * APu + kb];
                af[mf][1] = As[(m + 8) * APu + kb];
                af[mf][2] = As[m * APu + kb + 4];
                af[mf][3] = As[(m + 8) * APu + kb + 4];
            }
#pragma unroll
            for (int nf = 0; nf < NF; nf++) {
                int n = wn + nf * 8 + (lane >> 2);
                bfr[nf][0] = Bs[n * APu + kb];
                bfr[nf][1] = Bs[n * APu + kb + 4];
            }
#pragma unroll
            for (int mf = 0; mf < MF; mf++)
#pragma unroll
                for (int nf = 0; nf < NF; nf++)
                    mma_f16(acc[mf][nf], af[mf], bfr[nf]);
        }
    };

#pragma unroll
    for (int s = 0; s < S - 1; s++) {
        if (s < nch) load_stage(s, s);
        CP_COMMIT();
    }
    for (int kc = 0; kc < nch; kc++) {
        CP_WAIT(S - 2);
        __syncthreads();
        if (kc + S - 1 < nch) load_stage((kc + S - 1) % S, kc + S - 1);
        CP_COMMIT();
        compute_stage(kc % S);
        __syncthreads();
    }

#pragma unroll
    for (int mf = 0; mf < MF; mf++) {
#pragma unroll
        for (int nf = 0; nf < NF; nf++) {
            int row = wm + mf * 16 + (lane >> 2);
            int col = wn + nf * 8 + (lane & 3) * 2;
            float2 v0 = make_float2(rna_tf32(acc[mf][nf][0]),
                                    rna_tf32(acc[mf][nf][1]));
            float2 v1 = make_float2(rna_tf32(acc[mf][nf][2]),
                                    rna_tf32(acc[mf][nf][3]));
            *reinterpret_cast<float2*>(Cb + (long long)row * Ncols + col) = v0;
            *reinterpret_cast<float2*>(Cb + (long long)(row + 8) * Ncols + col) = v1;
        }
    }
}

// ---------------------------------------------------------------------------
// TF32 mma.sync GEMM + fused bias/LN/ReLU epilogues (BN == Ncols == 256).
// EPI_LN_TF16: writes H^T as fp16 into outT [b][256][2048].
// EPI_LN_COLSUM: accumulates column sums into colsum (no tensor store).
// ---------------------------------------------------------------------------
template <int EPI>
__global__ __launch_bounds__(256)
void tf32_ln_gemm(const float* __restrict__ A, const float* __restrict__ Bm,
                  int Kd,
                  const float* __restrict__ bias,
                  const float* __restrict__ gamma,
                  const float* __restrict__ beta,
                  float* __restrict__ colsum,
                  __half* __restrict__ outT) {
    constexpr int BM = 128, BK = 32, BN = 256, S = 2;
    constexpr int WROWS = 2, WCOLS = 4;
    constexpr int WM = BM / WROWS, WN = BN / WCOLS;
    constexpr int MF = WM / 16, NF = WN / 8;
    constexpr int AP = 36, BP = BN + 8;
    constexpr int AS_F = BM * AP, BS_F = BK * BP;
    constexpr int ST_F = AS_F + BS_F;
    constexpr int EP = 260;

    extern __shared__ float smem[];
    const uint32_t sbase = smem_u32(smem);

    const int tid = threadIdx.x, lane = tid & 31, wid = tid >> 5;
    const int wm = (wid / WCOLS) * WM, wn = (wid % WCOLS) * WN;

    const float* Ab = A + (long long)blockIdx.y * BM * Kd;

    float acc[MF][NF][4];
#pragma unroll
    for (int i = 0; i < MF; i++)
#pragma unroll
        for (int j = 0; j < NF; j++)
#pragma unroll
            for (int r = 0; r < 4; r++) acc[i][j][r] = 0.f;

    const int nch = Kd >> 5;

    auto load_stage = [&](int s, int kc) {
        const float* Ak = Ab + kc * BK;
#pragma unroll
        for (int i = 0; i < 4; i++) {
            int idx = tid + i * 256;
            int r = idx >> 3, c4 = idx & 7;
            cp16(sbase + (uint32_t)(s * ST_F + r * AP + c4 * 4) * 4u,
                 Ak + (long long)r * Kd + c4 * 4);
        }
        const float* Bk = Bm + (long long)(kc * BK) * BN;
#pragma unroll
        for (int i = 0; i < 8; i++) {
            int idx = tid + i * 256;
            int r = idx >> 6, c4 = idx & 63;
            cp16(sbase + (uint32_t)(s * ST_F + AS_F + r * BP + c4 * 4) * 4u,
                 Bk + (long long)r * BN + c4 * 4);
        }
    };

    auto compute_stage = [&](int s) {
        const uint32_t* As = reinterpret_cast<const uint32_t*>(smem + s * ST_F);
        const uint32_t* Bs = reinterpret_cast<const uint32_t*>(smem + s * ST_F + AS_F);
#pragma unroll
        for (int kk = 0; kk < 4; kk++) {
            const int k0 = kk * 8;
            uint32_t af[MF][4], bfr[NF][2];
#pragma unroll
            for (int mf = 0; mf < MF; mf++) {
                int m = wm + mf * 16 + (lane >> 2);
                int k = k0 + (lane & 3);
                af[mf][0] = As[m * AP + k];
                af[mf][1] = As[(m + 8) * AP + k];
                af[mf][2] = As[m * AP + k + 4];
                af[mf][3] = As[(m + 8) * AP + k + 4];
            }
#pragma unroll
            for (int nf = 0; nf < NF; nf++) {
                int n = wn + nf * 8 + (lane >> 2);
                int k = k0 + (lane & 3);
                bfr[nf][0] = Bs[k * BP + n];
                bfr[nf][1] = Bs[(k + 4) * BP + n];
            }
#pragma unroll
            for (int mf = 0; mf < MF; mf++)
#pragma unroll
                for (int nf = 0; nf < NF; nf++)
                    mma_tf32(acc[mf][nf], af[mf], bfr[nf]);
        }
    };

#pragma unroll
    for (int s = 0; s < S - 1; s++) {
        if (s < nch) load_stage(s, s);
        CP_COMMIT();
    }
    for (int kc = 0; kc < nch; kc++) {
        CP_WAIT(S - 2);
        __syncthreads();
        if (kc + S - 1 < nch) load_stage((kc + S - 1) % S, kc + S - 1);
        CP_COMMIT();
        compute_stage(kc % S);
        __syncthreads();
    }

    // ---- stash accumulators to smem tile [128][EP] ----
    __syncthreads();
#pragma unroll
    for (int mf = 0; mf < MF; mf++) {
#pragma unroll
        for (int nf = 0; nf < NF; nf++) {
            int row = wm + mf * 16 + (lane >> 2);
            int col = wn + nf * 8 + (lane & 3) * 2;
            smem[row * EP + col]     = acc[mf][nf][0];
            smem[row * EP + col + 1] = acc[mf][nf][1];
            smem[(row + 8) * EP + col]     = acc[mf][nf][2];
            smem[(row + 8) * EP + col + 1] = acc[mf][nf][3];
        }
    }
    __syncthreads();

    float rb[8], rg[8], rt[8];
#pragma unroll
    for (int j = 0; j < 8; j++) {
        rb[j] = __ldg(&bias[lane * 8 + j]);
        rg[j] = __ldg(&gamma[lane * 8 + j]);
        rt[j] = __ldg(&beta[lane * 8 + j]);
    }

    const float inv = 1.f / (float)HD_;
#pragma unroll 1
    for (int rr = 0; rr < 16; rr++) {
        const int r = wid * 16 + rr;
        float x[8];
        float4 v0 = *reinterpret_cast<float4*>(&smem[r * EP + lane * 8]);
        float4 v1 = *reinterpret_cast<float4*>(&smem[r * EP + lane * 8 + 4]);
        x[0] = v0.x; x[1] = v0.y; x[2] = v0.z; x[3] = v0.w;
        x[4] = v1.x; x[5] = v1.y; x[6] = v1.z; x[7] = v1.w;
        float s = 0.f, s2 = 0.f;
#pragma unroll
        for (int j = 0; j < 8; j++) {
            x[j] += rb[j];
            s += x[j]; s2 += x[j] * x[j];
        }
#pragma unroll
        for (int o = 16; o; o >>= 1) {
            s  += __shfl_xor_sync(0xFFFFFFFFu, s, o);
            s2 += __shfl_xor_sync(0xFFFFFFFFu, s2, o);
        }
        float mu = s * inv;
        float rstd = rsqrtf(s2 * inv - mu * mu + 1e-5f);
        float y[8];
#pragma unroll
        for (int j = 0; j < 8; j++) {
            float v = (x[j] - mu) * rstd * rg[j] + rt[j];
            y[j] = fmaxf(v, 0.f);
        }
        *reinterpret_cast<float4*>(&smem[r * EP + lane * 8]) =
            make_float4(y[0], y[1], y[2], y[3]);
        *reinterpret_cast<float4*>(&smem[r * EP + lane * 8 + 4]) =
            make_float4(y[4], y[5], y[6], y[7]);
    }
    __syncthreads();

    const int bb = (int)(blockIdx.y >> 4);       // batch (16 row-tiles each)

    if (EPI == EPI_LN_COLSUM) {
        float s = 0.f;
#pragma unroll 8
        for (int r = 0; r < BM; r++) s += smem[r * EP + tid];
        atomicAdd(&colsum[bb * HD_ + tid], s);
    } else {  // EPI_LN_TF16: thread owns column n=tid, write transposed fp16
        const int k0 = ((int)blockIdx.y & 15) * BM;
#pragma unroll 1
        for (int q = 0; q < 4; q++) {
            uint32_t pk[16];
#pragma unroll
            for (int r2 = 0; r2 < 16; r2++) {
                int r = q * 32 + 2 * r2;
                __half2 h2 = __float22half2_rn(
                    make_float2(smem[r * EP + tid], smem[(r + 1) * EP + tid]));
                pk[r2] = *reinterpret_cast<uint32_t*>(&h2);
            }
            uint4* dst = reinterpret_cast<uint4*>(
                outT + ((long long)(bb * HD_ + tid) * N_ + k0 + q * 32));
#pragma unroll
            for (int j = 0; j < 4; j++)
                dst[j] = make_uint4(pk[4 * j], pk[4 * j + 1],
                                    pk[4 * j + 2], pk[4 * j + 3]);
        }
    }
}

// ---------------------------------------------------------------------------
__global__ __launch_bounds__(256)
void head_kernel(const float* __restrict__ colsum, const float* __restrict__ gvec,
                 const float* __restrict__ Ws, const float* __restrict__ bs,
                 const float* __restrict__ Wa, const float* __restrict__ ba,
                 float* __restrict__ out) {
    int b = blockIdx.x, t = threadIdx.x;
    __shared__ float fused[FUSE_];
    fused[t] = colsum[b * HD_ + t] * (1.f / (float)N_);
    if (t < G_) fused[HD_ + t] = gvec[b * G_ + t];
    __syncthreads();

    if (t < K_) {
        float acc = ba[t];
#pragma unroll 4
        for (int i = 0; i < FUSE_; i++) acc += fused[i] * Wa[i * K_ + t];
        out[B_ + b * K_ + t] = acc;
    } else if (t == K_) {
        float acc = bs[0];
        for (int i = 0; i < FUSE_; i++) acc += fused[i] * Ws[i];
        out[b] = acc;
    }
}

// ---------------------------------------------------------------------------
extern "C" void kernel_launch(void* const* d_in, const int* in_sizes, int n_in,
                              void* d_out, int out_size) {
    const float* A_hat = (const float*)d_in[0];
    const float* X     = (const float*)d_in[1];
    const float* gvec  = (const float*)d_in[2];
    const float* W1    = (const float*)d_in[3];
    const float* b1    = (const float*)d_in[4];
    const float* g1    = (const float*)d_in[5];
    const float* be1   = (const float*)d_in[6];
    const float* W2    = (const float*)d_in[7];
    const float* b2    = (const float*)d_in[8];
    const float* g2    = (const float*)d_in[9];
    const float* be2   = (const float*)d_in[10];
    const float* Ws    = (const float*)d_in[11];
    const float* bs    = (const float*)d_in[12];
    const float* Wa    = (const float*)d_in[13];
    const float* ba    = (const float*)d_in[14];
    float* out = (float*)d_out;

    float *buf1, *buf2, *csum, *bW1, *bW2;
    __half *Ah, *XT, *H1T;
    cudaGetSymbolAddress((void**)&buf1, g_buf1);
    cudaGetSymbolAddress((void**)&buf2, g_buf2);
    cudaGetSymbolAddress((void**)&csum, g_colsum);
    cudaGetSymbolAddress((void**)&Ah,  g_Ah);
    cudaGetSymbolAddress((void**)&XT,  g_XT);
    cudaGetSymbolAddress((void**)&H1T, g_H1T);
    cudaGetSymbolAddress((void**)&bW1, g_bufW1);
    cudaGetSymbolAddress((void**)&bW2, g_bufW2);

    constexpr int SMEM_K1 = 4 * ((128 + 64) * 20) * 4;    // 61440
    constexpr int SMEM_K3 = 4 * ((128 + 128) * 20) * 4;   // 81920
    constexpr int SMEM_LN = 128 * 260 * 4;                // 133120

    auto k1 = f16_mma_gemm<64, 4, 2, 4, 2>;
    auto k3 = f16_mma_gemm<128, 2, 4, 4, 2>;
    auto k2 = tf32_ln_gemm<EPI_LN_TF16>;
    auto k4 = tf32_ln_gemm<EPI_LN_COLSUM>;

    cudaFuncSetAttribute((const void*)k1, cudaFuncAttributeMaxDynamicSharedMemorySize, SMEM_K1);
    cudaFuncSetAttribute((const void*)k3, cudaFuncAttributeMaxDynamicSharedMemorySize, SMEM_K3);
    cudaFuncSetAttribute((const void*)k2, cudaFuncAttributeMaxDynamicSharedMemorySize, SMEM_LN);
    cudaFuncSetAttribute((const void*)k4, cudaFuncAttributeMaxDynamicSharedMemorySize, SMEM_LN);

    // Prep: A_hat -> fp16 (one stream pass), X -> XT fp16, W -> tf32, csum=0
    convert_f16_kernel<<<(B_ * N_ * N_ / 4 + 255) / 256, 256>>>(
        A_hat, Ah, B_ * N_ * N_ / 4);
    transpose_x_kernel<<<dim3(F_ / 32, N_ / 32, B_), 256>>>(X, XT);
    round_tf32_kernel<<<(F_ * HD_ / 4 + 255) / 256, 256>>>(W1, bW1, F_ * HD_ / 4);
    round_tf32_kernel<<<(HD_ * HD_ / 4 + 255) / 256, 256>>>(W2, bW2, HD_ * HD_ / 4);
    cudaMemsetAsync(csum, 0, B_ * HD_ * sizeof(float));

    // K1: T1 = Ah @ XT^T   (fp16, per batch 2048x2048 @ 2048x64) -> buf1
    k1<<<dim3(1, 16, 16), 256, SMEM_K1>>>(
        Ah, XT, buf1, N_, F_,
        (long long)N_ * N_, (long long)F_ * N_, (long long)N_ * F_);
    // K2: H1T = fp16_T(relu(LN(T1 @ W1 + b1)))  (tf32, flat 32768x64 @ 64x256)
    k2<<<dim3(1, 256, 1), 256, SMEM_LN>>>(
        buf1, bW1, F_, b1, g1, be1, nullptr, H1T);
    // K3: T2 = Ah @ H1T^T  (fp16, per batch 2048x2048 @ 2048x256) -> buf2
    k3<<<dim3(2, 16, 16), 256, SMEM_K3>>>(
        Ah, H1T, buf2, N_, HD_,
        (long long)N_ * N_, (long long)HD_ * N_, (long long)N_ * HD_);
    // K4: colsum += colsums(relu(LN(T2 @ W2 + b2)))  (tf32)
    k4<<<dim3(1, 256, 1), 256, SMEM_LN>>>(
        buf2, bW2, HD_, b2, g2, be2, csum, nullptr);
    // K5: mean + concat + heads -> out
    head_kernel<<<B_, 256>>>(csum, gvec, Ws, bs, Wa, ba, out);
}

// round 10
// speedup vs baseline: 1.2776x; 1.0231x over previous
#include <cuda_runtime.h>
#include <cuda_fp16.h>
#include <cstdint>

// Problem constants
#define B_   16
#define N_   2048
#define F_   64
#define HD_  256
#define K_   128
#define G_   18
#define FUSE_ 274

// Scratch (allocation-free rule: __device__ globals)
__device__ float g_buf1[B_ * N_ * HD_];          // T1 (32768x64 used)
__device__ float g_buf2[B_ * N_ * HD_];          // T2
__device__ float g_colsum[B_ * HD_];
__device__ __half g_Ah[(size_t)B_ * N_ * N_];    // 134 MB fp16 A_hat (written by K1)
__device__ __half g_XT[B_ * F_ * N_];            // X^T fp16
__device__ __half g_H1T[B_ * HD_ * N_];          // H1^T fp16
__device__ float g_bufW1[F_ * HD_];
__device__ float g_bufW2[HD_ * HD_];

// Epilogue modes (tf32 LN kernel)
#define EPI_LN_TF16   1   // bias+LN+ReLU -> transposed fp16 store
#define EPI_LN_COLSUM 2   // bias+LN+ReLU -> column-sum atomics only

// ---------------------------------------------------------------------------
__device__ __forceinline__ uint32_t smem_u32(const void* p) {
    uint32_t a;
    asm("{ .reg .u64 t; cvta.to.shared.u64 t, %1; cvt.u32.u64 %0, t; }"
        : "=r"(a) : "l"(p));
    return a;
}

__device__ __forceinline__ void cp16(uint32_t dst, const void* src) {
    asm volatile("cp.async.cg.shared.global [%0], [%1], 16;"
                 :: "r"(dst), "l"(src) : "memory");
}
#define CP_COMMIT() asm volatile("cp.async.commit_group;" ::: "memory")
#define CP_WAIT(n)  asm volatile("cp.async.wait_group %0;" :: "n"(n) : "memory")

__device__ __forceinline__ float rna_tf32(float f) {
    uint32_t u;
    asm("cvt.rna.tf32.f32 %0, %1;" : "=r"(u) : "f"(f));
    return __uint_as_float(u);
}

__device__ __forceinline__ void mma_tf32(float* c, const uint32_t* a, const uint32_t* b) {
    asm volatile(
        "mma.sync.aligned.m16n8k8.row.col.f32.tf32.tf32.f32 "
        "{%0,%1,%2,%3}, {%4,%5,%6,%7}, {%8,%9}, {%0,%1,%2,%3};"
        : "+f"(c[0]), "+f"(c[1]), "+f"(c[2]), "+f"(c[3])
        : "r"(a[0]), "r"(a[1]), "r"(a[2]), "r"(a[3]), "r"(b[0]), "r"(b[1]));
}

__device__ __forceinline__ void mma_f16(float* c, const uint32_t* a, const uint32_t* b) {
    asm volatile(
        "mma.sync.aligned.m16n8k16.row.col.f32.f16.f16.f32 "
        "{%0,%1,%2,%3}, {%4,%5,%6,%7}, {%8,%9}, {%0,%1,%2,%3};"
        : "+f"(c[0]), "+f"(c[1]), "+f"(c[2]), "+f"(c[3])
        : "r"(a[0]), "r"(a[1]), "r"(a[2]), "r"(a[3]), "r"(b[0]), "r"(b[1]));
}

__device__ __forceinline__ uint32_t pack_h2(float a, float b) {
    __half2 h = __float22half2_rn(make_float2(a, b));
    return *reinterpret_cast<uint32_t*>(&h);
}

// ---------------------------------------------------------------------------
// X [b][2048][64] fp32 -> XT [b][64][2048] fp16
// ---------------------------------------------------------------------------
__global__ __launch_bounds__(256)
void transpose_x_kernel(const float* __restrict__ X, __half* __restrict__ XT) {
    __shared__ float t[32][33];
    int b = blockIdx.z, c0 = blockIdx.x * 32, r0 = blockIdx.y * 32;
    int tx = threadIdx.x & 31, ty = threadIdx.x >> 5;
    const float* Xb = X + (long long)b * N_ * F_;
#pragma unroll
    for (int i = 0; i < 4; i++)
        t[ty + i * 8][tx] = Xb[(long long)(r0 + ty + i * 8) * F_ + c0 + tx];
    __syncthreads();
    __half* XTb = XT + (long long)b * F_ * N_;
#pragma unroll
    for (int i = 0; i < 4; i++)
        XTb[(long long)(c0 + ty + i * 8) * N_ + r0 + tx] =
            __float2half_rn(t[tx][ty + i * 8]);
}

// ---------------------------------------------------------------------------
__global__ __launch_bounds__(256)
void round_tf32_kernel(const float* __restrict__ in, float* __restrict__ out, int n4) {
    int i = blockIdx.x * blockDim.x + threadIdx.x;
    if (i < n4) {
        float4 v = reinterpret_cast<const float4*>(in)[i];
        v.x = rna_tf32(v.x); v.y = rna_tf32(v.y);
        v.z = rna_tf32(v.z); v.w = rna_tf32(v.w);
        reinterpret_cast<float4*>(out)[i] = v;
    }
}

// ---------------------------------------------------------------------------
// K1 fused: T1[bz] = fp16(A[bz]) @ XT[bz]^T, and stream-convert A -> Ah fp16.
// A fp32 [2048][2048]; XT fp16 [64][2048]; T1 fp32 [2048][64] (rna-rounded).
// BM=128, BN=64, BK=32, 256 threads (8 warps, 32x32 warp tiles), S=3 stages.
// Per-stage smem (float/u32 units): A32[128*36]=4608 | A16[128*20]=2560 |
// B16[64*20]=1280 -> ST=8448 (33 KB).
// ---------------------------------------------------------------------------
template <int S, int MINB>
__global__ __launch_bounds__(256, MINB)
void k1_conv_gemm(const float* __restrict__ A, const __half* __restrict__ Bt,
                  float* __restrict__ C, __half* __restrict__ Ah) {
    constexpr int BM = 128, BN = 64, BK = 32;
    constexpr int MF = 2, NF = 4;        // warp tile 32x32, warp grid 4x2
    constexpr int A32P = 36;             // fp32 stage pitch (floats)
    constexpr int APu = 20;              // fp16 pitch (u32)
    constexpr int OFF_A16 = BM * A32P;           // 4608
    constexpr int OFF_B   = OFF_A16 + BM * APu;  // 7168
    constexpr int ST = OFF_B + BN * APu;         // 8448

    extern __shared__ uint32_t smu[];
    const uint32_t sbase = smem_u32(smu);

    const int tid = threadIdx.x, lane = tid & 31, wid = tid >> 5;
    const int wm = (wid >> 1) * 32, wn = (wid & 1) * 32;

    const long long bz = blockIdx.z;
    const long long bm = (long long)blockIdx.y * BM;
    const float*  Ab  = A  + (bz * N_ + bm) * N_;
    const __half* Btb = Bt + bz * (long long)F_ * N_;
    __half*       Ahb = Ah + (bz * N_ + bm) * N_;
    float*        Cb  = C  + (bz * N_ + bm) * F_;

    float acc[MF][NF][4];
#pragma unroll
    for (int i = 0; i < MF; i++)
#pragma unroll
        for (int j = 0; j < NF; j++)
#pragma unroll
            for (int r = 0; r < 4; r++) acc[i][j][r] = 0.f;

    constexpr int nch = N_ / BK;   // 64

    auto load_stage = [&](int s, int kc) {
        const float* Ak = Ab + kc * BK;
#pragma unroll
        for (int i = 0; i < 4; i++) {                 // 1024 float4 / 256 thr
            int idx = tid + i * 256;
            int r = idx >> 3, c4 = idx & 7;
            cp16(sbase + (uint32_t)(s * ST + r * A32P + c4 * 4) * 4u,
                 Ak + (long long)r * N_ + c4 * 4);
        }
        const __half* Bk = Btb + kc * BK;
        {                                              // 64 rows x 4 groups
            int n = tid >> 2, c8 = tid & 3;
            cp16(sbase + (uint32_t)(s * ST + OFF_B + n * APu + c8 * 4) * 4u,
                 Bk + (long long)n * N_ + c8 * 8);
        }
    };

    auto convert_stage = [&](int s, int kc) {
        const int cr = tid >> 1;             // row 0..127
        const int ch = (tid & 1) * 16;       // k offset 0 or 16
        const float* a32 = reinterpret_cast<const float*>(smu + s * ST) +
                           cr * A32P + ch;
        uint32_t h[8];
#pragma unroll
        for (int j = 0; j < 4; j++) {
            float4 v = *reinterpret_cast<const float4*>(a32 + j * 4);
            h[2 * j]     = pack_h2(v.x, v.y);
            h[2 * j + 1] = pack_h2(v.z, v.w);
        }
        uint32_t* a16 = smu + s * ST + OFF_A16 + cr * APu + (ch >> 1);
        *reinterpret_cast<uint4*>(a16)     = make_uint4(h[0], h[1], h[2], h[3]);
        *reinterpret_cast<uint4*>(a16 + 4) = make_uint4(h[4], h[5], h[6], h[7]);
        uint4* g = reinterpret_cast<uint4*>(Ahb + (long long)cr * N_ + kc * BK + ch);
        g[0] = make_uint4(h[0], h[1], h[2], h[3]);
        g[1] = make_uint4(h[4], h[5], h[6], h[7]);
    };

    auto compute_stage = [&](int s) {
        const uint32_t* As = smu + s * ST + OFF_A16;
        const uint32_t* Bs = smu + s * ST + OFF_B;
#pragma unroll
        for (int ks = 0; ks < 2; ks++) {
            const int kb = ks * 8 + (lane & 3);
            uint32_t af[MF][4], bfr[NF][2];
#pragma unroll
            for (int mf = 0; mf < MF; mf++) {
                int m = wm + mf * 16 + (lane >> 2);
                af[mf][0] = As[m * APu + kb];
                af[mf][1] = As[(m + 8) * APu + kb];
                af[mf][2] = As[m * APu + kb + 4];
                af[mf][3] = As[(m + 8) * APu + kb + 4];
            }
#pragma unroll
            for (int nf = 0; nf < NF; nf++) {
                int n = wn + nf * 8 + (lane >> 2);
                bfr[nf][0] = Bs[n * APu + kb];
                bfr[nf][1] = Bs[n * APu + kb + 4];
            }
#pragma unroll
            for (int mf = 0; mf < MF; mf++)
#pragma unroll
                for (int nf = 0; nf < NF; nf++)
                    mma_f16(acc[mf][nf], af[mf], bfr[nf]);
        }
    };

#pragma unroll
    for (int s = 0; s < S - 1; s++) {
        if (s < nch) load_stage(s, s);
        CP_COMMIT();
    }
    for (int kc = 0; kc < nch; kc++) {
        CP_WAIT(S - 2);
        __syncthreads();
        if (kc + S - 1 < nch) load_stage((kc + S - 1) % S, kc + S - 1);
        CP_COMMIT();
        convert_stage(kc % S, kc);
        __syncthreads();
        compute_stage(kc % S);
        __syncthreads();
    }

#pragma unroll
    for (int mf = 0; mf < MF; mf++) {
#pragma unroll
        for (int nf = 0; nf < NF; nf++) {
            int row = wm + mf * 16 + (lane >> 2);
            int col = wn + nf * 8 + (lane & 3) * 2;
            float2 v0 = make_float2(rna_tf32(acc[mf][nf][0]),
                                    rna_tf32(acc[mf][nf][1]));
            float2 v1 = make_float2(rna_tf32(acc[mf][nf][2]),
                                    rna_tf32(acc[mf][nf][3]));
            *reinterpret_cast<float2*>(Cb + (long long)row * F_ + col) = v0;
            *reinterpret_cast<float2*>(Cb + (long long)(row + 8) * F_ + col) = v1;
        }
    }
}

// ---------------------------------------------------------------------------
// FP16 mma.sync GEMM (K3): C[bz] = A[bz] @ Bt[bz]^T   (fp32 accumulate)
// A [M][Kd] fp16 row-major, Bt [Ncols][Kd] fp16 row-major.
// BM=128, BK=32, 256 threads. Output fp32, rna-rounded.
// ---------------------------------------------------------------------------
template <int BN, int WROWS, int WCOLS, int S, int MINB>
__global__ __launch_bounds__(256, MINB)
void f16_mma_gemm(const __half* __restrict__ A,
                  const __half* __restrict__ Bt,
                  float* __restrict__ C, int Kd, int Ncols,
                  long long sA, long long sB, long long sC) {
    constexpr int BM = 128, BK = 32;
    constexpr int WM = BM / WROWS, WN = BN / WCOLS;
    constexpr int MF = WM / 16, NF = WN / 8;
    constexpr int APu = 20;
    constexpr int AS_U = BM * APu;
    constexpr int BS_U = BN * APu;
    constexpr int ST_U = AS_U + BS_U;

    extern __shared__ uint32_t smu[];
    const uint32_t sbase = smem_u32(smu);

    const int tid = threadIdx.x, lane = tid & 31, wid = tid >> 5;
    const int wm = (wid / WCOLS) * WM, wn = (wid % WCOLS) * WN;
    const long long bz = blockIdx.z;
    const __half* Ab  = A  + bz * sA + (long long)blockIdx.y * BM * Kd;
    const __half* Btb = Bt + bz * sB + (long long)blockIdx.x * BN * Kd;
    float* Cb = C + bz * sC + (long long)blockIdx.y * BM * Ncols + blockIdx.x * BN;

    float acc[MF][NF][4];
#pragma unroll
    for (int i = 0; i < MF; i++)
#pragma unroll
        for (int j = 0; j < NF; j++)
#pragma unroll
            for (int r = 0; r < 4; r++) acc[i][j][r] = 0.f;

    const int nch = Kd >> 5;

    auto load_stage = [&](int s, int kc) {
        const __half* Ak = Ab + kc * BK;
#pragma unroll
        for (int i = 0; i < 2; i++) {
            int idx = tid + i * 256;
            int r = idx >> 2, c8 = idx & 3;
            cp16(sbase + (uint32_t)(s * ST_U + r * APu + c8 * 4) * 4u,
                 Ak + (long long)r * Kd + c8 * 8);
        }
        const __half* Bk = Btb + kc * BK;
#pragma unroll
        for (int i = 0; i < BN / 64; i++) {
            int idx = tid + i * 256;
            int n = idx >> 2, c8 = idx & 3;
            cp16(sbase + (uint32_t)(s * ST_U + AS_U + n * APu + c8 * 4) * 4u,
                 Bk + (long long)n * Kd + c8 * 8);
        }
    };

    auto compute_stage = [&](int s) {
        const uint32_t* As = smu + s * ST_U;
        const uint32_t* Bs = smu + s * ST_U + AS_U;
#pragma unroll
        for (int ks = 0; ks < 2; ks++) {
            const int kb = ks * 8 + (lane & 3);
            uint32_t af[MF][4], bfr[NF][2];
#pragma unroll
            for (int mf = 0; mf < MF; mf++) {
                int m = wm + mf * 16 + (lane >> 2);
                af[mf][0] = As[m * APu + kb];
                af[mf][1] = As[(m + 8) * APu + kb];
                af[mf][2] = As[m * APu + kb + 4];
                af[mf][3] = As[(m + 8) * APu + kb + 4];
            }
#pragma unroll
            for (int nf = 0; nf < NF; nf++) {
                int n = wn + nf * 8 + (lane >> 2);
                bfr[nf][0] = Bs[n * APu + kb];
                bfr[nf][1] = Bs[n * APu + kb + 4];
            }
#pragma unroll
            for (int mf = 0; mf < MF; mf++)
#pragma unroll
                for (int nf = 0; nf < NF; nf++)
                    mma_f16(acc[mf][nf], af[mf], bfr[nf]);
        }
    };

#pragma unroll
    for (int s = 0; s < S - 1; s++) {
        if (s < nch) load_stage(s, s);
        CP_COMMIT();
    }
    for (int kc = 0; kc < nch; kc++) {
        CP_WAIT(S - 2);
        __syncthreads();
        if (kc + S - 1 < nch) load_stage((kc + S - 1) % S, kc + S - 1);
        CP_COMMIT();
        compute_stage(kc % S);
        __syncthreads();
    }

#pragma unroll
    for (int mf = 0; mf < MF; mf++) {
#pragma unroll
        for (int nf = 0; nf < NF; nf++) {
            int row = wm + mf * 16 + (lane >> 2);
            int col = wn + nf * 8 + (lane & 3) * 2;
            float2 v0 = make_float2(rna_tf32(acc[mf][nf][0]),
                                    rna_tf32(acc[mf][nf][1]));
            float2 v1 = make_float2(rna_tf32(acc[mf][nf][2]),
                                    rna_tf32(acc[mf][nf][3]));
            *reinterpret_cast<float2*>(Cb + (long long)row * Ncols + col) = v0;
            *reinterpret_cast<float2*>(Cb + (long long)(row + 8) * Ncols + col) = v1;
        }
    }
}

// ---------------------------------------------------------------------------
// TF32 mma.sync GEMM + fused bias/LN/ReLU epilogues (BN == Ncols == 256).
// EPI_LN_TF16: writes H^T as fp16 into outT [b][256][2048].
// EPI_LN_COLSUM: accumulates column sums into colsum (no tensor store).
// ---------------------------------------------------------------------------
template <int EPI>
__global__ __launch_bounds__(256)
void tf32_ln_gemm(const float* __restrict__ A, const float* __restrict__ Bm,
                  int Kd,
                  const float* __restrict__ bias,
                  const float* __restrict__ gamma,
                  const float* __restrict__ beta,
                  float* __restrict__ colsum,
                  __half* __restrict__ outT) {
    constexpr int BM = 128, BK = 32, BN = 256, S = 2;
    constexpr int WROWS = 2, WCOLS = 4;
    constexpr int WM = BM / WROWS, WN = BN / WCOLS;
    constexpr int MF = WM / 16, NF = WN / 8;
    constexpr int AP = 36, BP = BN + 8;
    constexpr int AS_F = BM * AP, BS_F = BK * BP;
    constexpr int ST_F = AS_F + BS_F;
    constexpr int EP = 260;

    extern __shared__ float smem[];
    const uint32_t sbase = smem_u32(smem);

    const int tid = threadIdx.x, lane = tid & 31, wid = tid >> 5;
    const int wm = (wid / WCOLS) * WM, wn = (wid % WCOLS) * WN;

    const float* Ab = A + (long long)blockIdx.y * BM * Kd;

    float acc[MF][NF][4];
#pragma unroll
    for (int i = 0; i < MF; i++)
#pragma unroll
        for (int j = 0; j < NF; j++)
#pragma unroll
            for (int r = 0; r < 4; r++) acc[i][j][r] = 0.f;

    const int nch = Kd >> 5;

    auto load_stage = [&](int s, int kc) {
        const float* Ak = Ab + kc * BK;
#pragma unroll
        for (int i = 0; i < 4; i++) {
            int idx = tid + i * 256;
            int r = idx >> 3, c4 = idx & 7;
            cp16(sbase + (uint32_t)(s * ST_F + r * AP + c4 * 4) * 4u,
                 Ak + (long long)r * Kd + c4 * 4);
        }
        const float* Bk = Bm + (long long)(kc * BK) * BN;
#pragma unroll
        for (int i = 0; i < 8; i++) {
            int idx = tid + i * 256;
            int r = idx >> 6, c4 = idx & 63;
            cp16(sbase + (uint32_t)(s * ST_F + AS_F + r * BP + c4 * 4) * 4u,
                 Bk + (long long)r * BN + c4 * 4);
        }
    };

    auto compute_stage = [&](int s) {
        const uint32_t* As = reinterpret_cast<const uint32_t*>(smem + s * ST_F);
        const uint32_t* Bs = reinterpret_cast<const uint32_t*>(smem + s * ST_F + AS_F);
#pragma unroll
        for (int kk = 0; kk < 4; kk++) {
            const int k0 = kk * 8;
            uint32_t af[MF][4], bfr[NF][2];
#pragma unroll
            for (int mf = 0; mf < MF; mf++) {
                int m = wm + mf * 16 + (lane >> 2);
                int k = k0 + (lane & 3);
                af[mf][0] = As[m * AP + k];
                af[mf][1] = As[(m + 8) * AP + k];
                af[mf][2] = As[m * AP + k + 4];
                af[mf][3] = As[(m + 8) * AP + k + 4];
            }
#pragma unroll
            for (int nf = 0; nf < NF; nf++) {
                int n = wn + nf * 8 + (lane >> 2);
                int k = k0 + (lane & 3);
                bfr[nf][0] = Bs[k * BP + n];
                bfr[nf][1] = Bs[(k + 4) * BP + n];
            }
#pragma unroll
            for (int mf = 0; mf < MF; mf++)
#pragma unroll
                for (int nf = 0; nf < NF; nf++)
                    mma_tf32(acc[mf][nf], af[mf], bfr[nf]);
        }
    };

#pragma unroll
    for (int s = 0; s < S - 1; s++) {
        if (s < nch) load_stage(s, s);
        CP_COMMIT();
    }
    for (int kc = 0; kc < nch; kc++) {
        CP_WAIT(S - 2);
        __syncthreads();
        if (kc + S - 1 < nch) load_stage((kc + S - 1) % S, kc + S - 1);
        CP_COMMIT();
        compute_stage(kc % S);
        __syncthreads();
    }

    // ---- stash accumulators to smem tile [128][EP] ----
    __syncthreads();
#pragma unroll
    for (int mf = 0; mf < MF; mf++) {
#pragma unroll
        for (int nf = 0; nf < NF; nf++) {
            int row = wm + mf * 16 + (lane >> 2);
            int col = wn + nf * 8 + (lane & 3) * 2;
            smem[row * EP + col]     = acc[mf][nf][0];
            smem[row * EP + col + 1] = acc[mf][nf][1];
            smem[(row + 8) * EP + col]     = acc[mf][nf][2];
            smem[(row + 8) * EP + col + 1] = acc[mf][nf][3];
        }
    }
    __syncthreads();

    float rb[8], rg[8], rt[8];
#pragma unroll
    for (int j = 0; j < 8; j++) {
        rb[j] = __ldg(&bias[lane * 8 + j]);
        rg[j] = __ldg(&gamma[lane * 8 + j]);
        rt[j] = __ldg(&beta[lane * 8 + j]);
    }

    const float inv = 1.f / (float)HD_;
#pragma unroll 1
    for (int rr = 0; rr < 16; rr++) {
        const int r = wid * 16 + rr;
        float x[8];
        float4 v0 = *reinterpret_cast<float4*>(&smem[r * EP + lane * 8]);
        float4 v1 = *reinterpret_cast<float4*>(&smem[r * EP + lane * 8 + 4]);
        x[0] = v0.x; x[1] = v0.y; x[2] = v0.z; x[3] = v0.w;
        x[4] = v1.x; x[5] = v1.y; x[6] = v1.z; x[7] = v1.w;
        float s = 0.f, s2 = 0.f;
#pragma unroll
        for (int j = 0; j < 8; j++) {
            x[j] += rb[j];
            s += x[j]; s2 += x[j] * x[j];
        }
#pragma unroll
        for (int o = 16; o; o >>= 1) {
            s  += __shfl_xor_sync(0xFFFFFFFFu, s, o);
            s2 += __shfl_xor_sync(0xFFFFFFFFu, s2, o);
        }
        float mu = s * inv;
        float rstd = rsqrtf(s2 * inv - mu * mu + 1e-5f);
        float y[8];
#pragma unroll
        for (int j = 0; j < 8; j++) {
            float v = (x[j] - mu) * rstd * rg[j] + rt[j];
            y[j] = fmaxf(v, 0.f);
        }
        *reinterpret_cast<float4*>(&smem[r * EP + lane * 8]) =
            make_float4(y[0], y[1], y[2], y[3]);
        *reinterpret_cast<float4*>(&smem[r * EP + lane * 8 + 4]) =
            make_float4(y[4], y[5], y[6], y[7]);
    }
    __syncthreads();

    const int bb = (int)(blockIdx.y >> 4);       // batch (16 row-tiles each)

    if (EPI == EPI_LN_COLSUM) {
        float s = 0.f;
#pragma unroll 8
        for (int r = 0; r < BM; r++) s += smem[r * EP + tid];
        atomicAdd(&colsum[bb * HD_ + tid], s);
    } else {  // EPI_LN_TF16: thread owns column n=tid, write transposed fp16
        const int k0 = ((int)blockIdx.y & 15) * BM;
#pragma unroll 1
        for (int q = 0; q < 4; q++) {
            uint32_t pk[16];
#pragma unroll
            for (int r2 = 0; r2 < 16; r2++) {
                int r = q * 32 + 2 * r2;
                pk[r2] = pack_h2(smem[r * EP + tid], smem[(r + 1) * EP + tid]);
            }
            uint4* dst = reinterpret_cast<uint4*>(
                outT + ((long long)(bb * HD_ + tid) * N_ + k0 + q * 32));
#pragma unroll
            for (int j = 0; j < 4; j++)
                dst[j] = make_uint4(pk[4 * j], pk[4 * j + 1],
                                    pk[4 * j + 2], pk[4 * j + 3]);
        }
    }
}

// ---------------------------------------------------------------------------
__global__ __launch_bounds__(256)
void head_kernel(const float* __restrict__ colsum, const float* __restrict__ gvec,
                 const float* __restrict__ Ws, const float* __restrict__ bs,
                 const float* __restrict__ Wa, const float* __restrict__ ba,
                 float* __restrict__ out) {
    int b = blockIdx.x, t = threadIdx.x;
    __shared__ float fused[FUSE_];
    fused[t] = colsum[b * HD_ + t] * (1.f / (float)N_);
    if (t < G_) fused[HD_ + t] = gvec[b * G_ + t];
    __syncthreads();

    if (t < K_) {
        float acc = ba[t];
#pragma unroll 4
        for (int i = 0; i < FUSE_; i++) acc += fused[i] * Wa[i * K_ + t];
        out[B_ + b * K_ + t] = acc;
    } else if (t == K_) {
        float acc = bs[0];
        for (int i = 0; i < FUSE_; i++) acc += fused[i] * Ws[i];
        out[b] = acc;
    }
}

// ---------------------------------------------------------------------------
extern "C" void kernel_launch(void* const* d_in, const int* in_sizes, int n_in,
                              void* d_out, int out_size) {
    const float* A_hat = (const float*)d_in[0];
    const float* X     = (const float*)d_in[1];
    const float* gvec  = (const float*)d_in[2];
    const float* W1    = (const float*)d_in[3];
    const float* b1    = (const float*)d_in[4];
    const float* g1    = (const float*)d_in[5];
    const float* be1   = (const float*)d_in[6];
    const float* W2    = (const float*)d_in[7];
    const float* b2    = (const float*)d_in[8];
    const float* g2    = (const float*)d_in[9];
    const float* be2   = (const float*)d_in[10];
    const float* Ws    = (const float*)d_in[11];
    const float* bs    = (const float*)d_in[12];
    const float* Wa    = (const float*)d_in[13];
    const float* ba    = (const float*)d_in[14];
    float* out = (float*)d_out;

    float *buf1, *buf2, *csum, *bW1, *bW2;
    __half *Ah, *XT, *H1T;
    cudaGetSymbolAddress((void**)&buf1, g_buf1);
    cudaGetSymbolAddress((void**)&buf2, g_buf2);
    cudaGetSymbolAddress((void**)&csum, g_colsum);
    cudaGetSymbolAddress((void**)&Ah,  g_Ah);
    cudaGetSymbolAddress((void**)&XT,  g_XT);
    cudaGetSymbolAddress((void**)&H1T, g_H1T);
    cudaGetSymbolAddress((void**)&bW1, g_bufW1);
    cudaGetSymbolAddress((void**)&bW2, g_bufW2);

    constexpr int SMEM_K1 = 3 * 8448 * 4;                 // 101376
    constexpr int SMEM_K3 = 4 * ((128 + 128) * 20) * 4;   // 81920
    constexpr int SMEM_LN = 128 * 260 * 4;                // 133120

    auto k1 = k1_conv_gemm<3, 2>;
    auto k3 = f16_mma_gemm<128, 2, 4, 4, 2>;
    auto k2 = tf32_ln_gemm<EPI_LN_TF16>;
    auto k4 = tf32_ln_gemm<EPI_LN_COLSUM>;

    cudaFuncSetAttribute((const void*)k1, cudaFuncAttributeMaxDynamicSharedMemorySize, SMEM_K1);
    cudaFuncSetAttribute((const void*)k3, cudaFuncAttributeMaxDynamicSharedMemorySize, SMEM_K3);
    cudaFuncSetAttribute((const void*)k2, cudaFuncAttributeMaxDynamicSharedMemorySize, SMEM_LN);
    cudaFuncSetAttribute((const void*)k4, cudaFuncAttributeMaxDynamicSharedMemorySize, SMEM_LN);

    // Prep: X -> XT fp16, W -> tf32, csum = 0
    transpose_x_kernel<<<dim3(F_ / 32, N_ / 32, B_), 256>>>(X, XT);
    round_tf32_kernel<<<(F_ * HD_ / 4 + 255) / 256, 256>>>(W1, bW1, F_ * HD_ / 4);
    round_tf32_kernel<<<(HD_ * HD_ / 4 + 255) / 256, 256>>>(W2, bW2, HD_ * HD_ / 4);
    cudaMemsetAsync(csum, 0, B_ * HD_ * sizeof(float));

    // K1 (fused): T1 = fp16(A_hat) @ XT^T -> buf1; also writes Ah fp16
    k1<<<dim3(1, 16, 16), 256, SMEM_K1>>>(A_hat, XT, buf1, Ah);
    // K2: H1T = fp16_T(relu(LN(T1 @ W1 + b1)))  (tf32, flat 32768x64 @ 64x256)
    k2<<<dim3(1, 256, 1), 256, SMEM_LN>>>(
        buf1, bW1, F_, b1, g1, be1, nullptr, H1T);
    // K3: T2 = Ah @ H1T^T  (fp16, per batch 2048x2048 @ 2048x256) -> buf2
    k3<<<dim3(2, 16, 16), 256, SMEM_K3>>>(
        Ah, H1T, buf2, N_, HD_,
        (long long)N_ * N_, (long long)HD_ * N_, (long long)N_ * HD_);
    // K4: colsum += colsums(relu(LN(T2 @ W2 + b2)))  (tf32)
    k4<<<dim3(1, 256, 1), 256, SMEM_LN>>>(
        buf2, bW2, HD_, b2, g2, be2, csum, nullptr);
    // K5: mean + concat + heads -> out
    head_kernel<<<B_, 256>>>(csum, gvec, Ws, bs, Wa, ba, out);
}

// round 11
// speedup vs baseline: 1.2801x; 1.0020x over previous
#include <cuda_runtime.h>
#include <cuda_fp16.h>
#include <cstdint>

// Problem constants
#define B_   16
#define N_   2048
#define F_   64
#define HD_  256
#define K_   128
#define G_   18
#define FUSE_ 274

// Scratch (allocation-free rule: __device__ globals)
__device__ float g_buf1[B_ * N_ * HD_];          // T1 (32768x64 used)
__device__ float g_buf2[B_ * N_ * HD_];          // T2
__device__ float g_colsum[B_ * HD_];
__device__ __half g_Ah[(size_t)B_ * N_ * N_];    // 134 MB fp16 A_hat (written by K1)
__device__ __half g_XT[B_ * F_ * N_];            // X^T fp16
__device__ __half g_H1T[B_ * HD_ * N_];          // H1^T fp16
__device__ float g_bufW1[F_ * HD_];
__device__ float g_bufW2[HD_ * HD_];

// Epilogue modes (tf32 LN kernel)
#define EPI_LN_TF16   1   // bias+LN+ReLU -> transposed fp16 store
#define EPI_LN_COLSUM 2   // bias+LN+ReLU -> column-sum atomics only

// ---------------------------------------------------------------------------
__device__ __forceinline__ uint32_t smem_u32(const void* p) {
    uint32_t a;
    asm("{ .reg .u64 t; cvta.to.shared.u64 t, %1; cvt.u32.u64 %0, t; }"
        : "=r"(a) : "l"(p));
    return a;
}

__device__ __forceinline__ void cp16(uint32_t dst, const void* src) {
    asm volatile("cp.async.cg.shared.global [%0], [%1], 16;"
                 :: "r"(dst), "l"(src) : "memory");
}
#define CP_COMMIT() asm volatile("cp.async.commit_group;" ::: "memory")
#define CP_WAIT(n)  asm volatile("cp.async.wait_group %0;" :: "n"(n) : "memory")

__device__ __forceinline__ float rna_tf32(float f) {
    uint32_t u;
    asm("cvt.rna.tf32.f32 %0, %1;" : "=r"(u) : "f"(f));
    return __uint_as_float(u);
}

__device__ __forceinline__ void mma_tf32(float* c, const uint32_t* a, const uint32_t* b) {
    asm volatile(
        "mma.sync.aligned.m16n8k8.row.col.f32.tf32.tf32.f32 "
        "{%0,%1,%2,%3}, {%4,%5,%6,%7}, {%8,%9}, {%0,%1,%2,%3};"
        : "+f"(c[0]), "+f"(c[1]), "+f"(c[2]), "+f"(c[3])
        : "r"(a[0]), "r"(a[1]), "r"(a[2]), "r"(a[3]), "r"(b[0]), "r"(b[1]));
}

__device__ __forceinline__ void mma_f16(float* c, const uint32_t* a, const uint32_t* b) {
    asm volatile(
        "mma.sync.aligned.m16n8k16.row.col.f32.f16.f16.f32 "
        "{%0,%1,%2,%3}, {%4,%5,%6,%7}, {%8,%9}, {%0,%1,%2,%3};"
        : "+f"(c[0]), "+f"(c[1]), "+f"(c[2]), "+f"(c[3])
        : "r"(a[0]), "r"(a[1]), "r"(a[2]), "r"(a[3]), "r"(b[0]), "r"(b[1]));
}

__device__ __forceinline__ uint32_t pack_h2(float a, float b) {
    __half2 h = __float22half2_rn(make_float2(a, b));
    return *reinterpret_cast<uint32_t*>(&h);
}

// ---------------------------------------------------------------------------
// X [b][2048][64] fp32 -> XT [b][64][2048] fp16
// ---------------------------------------------------------------------------
__global__ __launch_bounds__(256)
void transpose_x_kernel(const float* __restrict__ X, __half* __restrict__ XT) {
    __shared__ float t[32][33];
    int b = blockIdx.z, c0 = blockIdx.x * 32, r0 = blockIdx.y * 32;
    int tx = threadIdx.x & 31, ty = threadIdx.x >> 5;
    const float* Xb = X + (long long)b * N_ * F_;
#pragma unroll
    for (int i = 0; i < 4; i++)
        t[ty + i * 8][tx] = Xb[(long long)(r0 + ty + i * 8) * F_ + c0 + tx];
    __syncthreads();
    __half* XTb = XT + (long long)b * F_ * N_;
#pragma unroll
    for (int i = 0; i < 4; i++)
        XTb[(long long)(c0 + ty + i * 8) * N_ + r0 + tx] =
            __float2half_rn(t[tx][ty + i * 8]);
}

// ---------------------------------------------------------------------------
__global__ __launch_bounds__(256)
void round_tf32_kernel(const float* __restrict__ in, float* __restrict__ out, int n4) {
    int i = blockIdx.x * blockDim.x + threadIdx.x;
    if (i < n4) {
        float4 v = reinterpret_cast<const float4*>(in)[i];
        v.x = rna_tf32(v.x); v.y = rna_tf32(v.y);
        v.z = rna_tf32(v.z); v.w = rna_tf32(v.w);
        reinterpret_cast<float4*>(out)[i] = v;
    }
}

// ---------------------------------------------------------------------------
// K1 fused (register-staged): T1[bz] = fp16(A[bz]) @ XT[bz]^T; A -> Ah fp16.
// A fp32 [2048][2048]; XT fp16 [64][2048]; T1 fp32 [2048][64] (rna-rounded).
// BM=128, BN=64, BK=32, 256 threads (8 warps, 32x32 warp tiles).
// A chunk lives in registers (float4 x4 per thread = one 128x32 tile across
// the CTA); converted to fp16 into a 2-deep smem ring. B via cp.async with a
// 3-deep ring. ONE barrier per K-chunk.
// Buffer-reuse safety: STS(kc+2 -> Abuf[kc&1]) happens after bar(kc+1), and
// every warp reaching bar(kc+1) has executed compute(kc) (program order), so
// the 2-deep A ring is race-free; cp.async(kc+1 -> Bbuf[(kc+1)%3]) is issued
// after bar(kc-1)... 3-deep B ring covers the one-iteration issue lead.
// ---------------------------------------------------------------------------
template <int MINB>
__global__ __launch_bounds__(256, MINB)
void k1_conv_gemm(const float* __restrict__ A, const __half* __restrict__ Bt,
                  float* __restrict__ C, __half* __restrict__ Ah) {
    constexpr int BM = 128, BN = 64, BK = 32;
    constexpr int MF = 2, NF = 4;            // warp tile 32x32, warp grid 4x2
    constexpr int APu = 20;                  // fp16 pitch (u32)
    constexpr int ABUF = BM * APu;           // 2560 u32 per A stage
    constexpr int OFF_B = 2 * ABUF;          // 5120
    constexpr int BBUF = BN * APu;           // 1280 u32 per B stage
    // total smem: 5120 + 3*1280 = 8960 u32 = 35840 B

    extern __shared__ uint32_t smu[];
    const uint32_t sbase = smem_u32(smu);

    const int tid = threadIdx.x, lane = tid & 31, wid = tid >> 5;
    const int wm = (wid >> 1) * 32, wn = (wid & 1) * 32;

    const long long bz = blockIdx.z;
    const long long bm = (long long)blockIdx.y * BM;
    const float*  Ab  = A  + (bz * N_ + bm) * N_;
    const __half* Btb = Bt + bz * (long long)F_ * N_;
    __half*       Ahb = Ah + (bz * N_ + bm) * N_;
    float*        Cb  = C  + (bz * N_ + bm) * F_;

    const int cr = tid >> 1;             // A row 0..127 owned by this thread
    const int ch = (tid & 1) * 16;       // k offset 0 or 16
    const float* Arow = Ab + (long long)cr * N_ + ch;
    __half* AhRow = Ahb + (long long)cr * N_ + ch;

    float acc[MF][NF][4];
#pragma unroll
    for (int i = 0; i < MF; i++)
#pragma unroll
        for (int j = 0; j < NF; j++)
#pragma unroll
            for (int r = 0; r < 4; r++) acc[i][j][r] = 0.f;

    constexpr int nch = N_ / BK;   // 64

    auto load_B = [&](int s, int kc) {
        int n = tid >> 2, c8 = tid & 3;        // 64 rows x 4 cp16 groups
        cp16(sbase + (uint32_t)(OFF_B + s * BBUF + n * APu + c8 * 4) * 4u,
             Btb + (long long)n * N_ + kc * BK + c8 * 8);
    };

    float4 a32[4];
    auto ldgA = [&](int kc) {
        const float4* p = reinterpret_cast<const float4*>(Arow + kc * BK);
#pragma unroll
        for (int j = 0; j < 4; j++) a32[j] = p[j];
    };

    // Prologue
    load_B(0, 0);
    CP_COMMIT();
    ldgA(0);

    for (int kc = 0; kc < nch; kc++) {
        const int sa = kc & 1;
        // convert current A chunk (regs) -> fp16 smem + fp16 gmem
        uint32_t h[8];
#pragma unroll
        for (int j = 0; j < 4; j++) {
            h[2 * j]     = pack_h2(a32[j].x, a32[j].y);
            h[2 * j + 1] = pack_h2(a32[j].z, a32[j].w);
        }
        uint32_t* a16 = smu + sa * ABUF + cr * APu + (ch >> 1);
        *reinterpret_cast<uint4*>(a16)     = make_uint4(h[0], h[1], h[2], h[3]);
        *reinterpret_cast<uint4*>(a16 + 4) = make_uint4(h[4], h[5], h[6], h[7]);
        uint4* g = reinterpret_cast<uint4*>(AhRow + kc * BK);
        g[0] = make_uint4(h[0], h[1], h[2], h[3]);
        g[1] = make_uint4(h[4], h[5], h[6], h[7]);

        // issue next chunk's loads (overlap with this chunk's MMA)
        if (kc + 1 < nch) {
            ldgA(kc + 1);
            load_B((kc + 1) % 3, kc + 1);
        }
        CP_COMMIT();
        CP_WAIT(1);          // B(kc) resident
        __syncthreads();     // fp16 A tile + B tile visible; ring reuse safe

        const uint32_t* As = smu + sa * ABUF;
        const uint32_t* Bs = smu + OFF_B + (kc % 3) * BBUF;
#pragma unroll
        for (int ks = 0; ks < 2; ks++) {
            const int kb = ks * 8 + (lane & 3);
            uint32_t af[MF][4], bfr[NF][2];
#pragma unroll
            for (int mf = 0; mf < MF; mf++) {
                int m = wm + mf * 16 + (lane >> 2);
                af[mf][0] = As[m * APu + kb];
                af[mf][1] = As[(m + 8) * APu + kb];
                af[mf][2] = As[m * APu + kb + 4];
                af[mf][3] = As[(m + 8) * APu + kb + 4];
            }
#pragma unroll
            for (int nf = 0; nf < NF; nf++) {
                int n = wn + nf * 8 + (lane >> 2);
                bfr[nf][0] = Bs[n * APu + kb];
                bfr[nf][1] = Bs[n * APu + kb + 4];
            }
#pragma unroll
            for (int mf = 0; mf < MF; mf++)
#pragma unroll
                for (int nf = 0; nf < NF; nf++)
                    mma_f16(acc[mf][nf], af[mf], bfr[nf]);
        }
    }

#pragma unroll
    for (int mf = 0; mf < MF; mf++) {
#pragma unroll
        for (int nf = 0; nf < NF; nf++) {
            int row = wm + mf * 16 + (lane >> 2);
            int col = wn + nf * 8 + (lane & 3) * 2;
            float2 v0 = make_float2(rna_tf32(acc[mf][nf][0]),
                                    rna_tf32(acc[mf][nf][1]));
            float2 v1 = make_float2(rna_tf32(acc[mf][nf][2]),
                                    rna_tf32(acc[mf][nf][3]));
            *reinterpret_cast<float2*>(Cb + (long long)row * F_ + col) = v0;
            *reinterpret_cast<float2*>(Cb + (long long)(row + 8) * F_ + col) = v1;
        }
    }
}

// ---------------------------------------------------------------------------
// FP16 mma.sync GEMM (K3): C[bz] = A[bz] @ Bt[bz]^T   (fp32 accumulate)
// A [M][Kd] fp16 row-major, Bt [Ncols][Kd] fp16 row-major.
// BM=128, BK=32, 256 threads. Output fp32, rna-rounded.
// ---------------------------------------------------------------------------
template <int BN, int WROWS, int WCOLS, int S, int MINB>
__global__ __launch_bounds__(256, MINB)
void f16_mma_gemm(const __half* __restrict__ A,
                  const __half* __restrict__ Bt,
                  float* __restrict__ C, int Kd, int Ncols,
                  long long sA, long long sB, long long sC) {
    constexpr int BM = 128, BK = 32;
    constexpr int WM = BM / WROWS, WN = BN / WCOLS;
    constexpr int MF = WM / 16, NF = WN / 8;
    constexpr int APu = 20;
    constexpr int AS_U = BM * APu;
    constexpr int BS_U = BN * APu;
    constexpr int ST_U = AS_U + BS_U;

    extern __shared__ uint32_t smu[];
    const uint32_t sbase = smem_u32(smu);

    const int tid = threadIdx.x, lane = tid & 31, wid = tid >> 5;
    const int wm = (wid / WCOLS) * WM, wn = (wid % WCOLS) * WN;
    const long long bz = blockIdx.z;
    const __half* Ab  = A  + bz * sA + (long long)blockIdx.y * BM * Kd;
    const __half* Btb = Bt + bz * sB + (long long)blockIdx.x * BN * Kd;
    float* Cb = C + bz * sC + (long long)blockIdx.y * BM * Ncols + blockIdx.x * BN;

    float acc[MF][NF][4];
#pragma unroll
    for (int i = 0; i < MF; i++)
#pragma unroll
        for (int j = 0; j < NF; j++)
#pragma unroll
            for (int r = 0; r < 4; r++) acc[i][j][r] = 0.f;

    const int nch = Kd >> 5;

    auto load_stage = [&](int s, int kc) {
        const __half* Ak = Ab + kc * BK;
#pragma unroll
        for (int i = 0; i < 2; i++) {
            int idx = tid + i * 256;
            int r = idx >> 2, c8 = idx & 3;
            cp16(sbase + (uint32_t)(s * ST_U + r * APu + c8 * 4) * 4u,
                 Ak + (long long)r * Kd + c8 * 8);
        }
        const __half* Bk = Btb + kc * BK;
#pragma unroll
        for (int i = 0; i < BN / 64; i++) {
            int idx = tid + i * 256;
            int n = idx >> 2, c8 = idx & 3;
            cp16(sbase + (uint32_t)(s * ST_U + AS_U + n * APu + c8 * 4) * 4u,
                 Bk + (long long)n * Kd + c8 * 8);
        }
    };

    auto compute_stage = [&](int s) {
        const uint32_t* As = smu + s * ST_U;
        const uint32_t* Bs = smu + s * ST_U + AS_U;
#pragma unroll
        for (int ks = 0; ks < 2; ks++) {
            const int kb = ks * 8 + (lane & 3);
            uint32_t af[MF][4], bfr[NF][2];
#pragma unroll
            for (int mf = 0; mf < MF; mf++) {
                int m = wm + mf * 16 + (lane >> 2);
                af[mf][0] = As[m * APu + kb];
                af[mf][1] = As[(m + 8) * APu + kb];
                af[mf][2] = As[m * APu + kb + 4];
                af[mf][3] = As[(m + 8) * APu + kb + 4];
            }
#pragma unroll
            for (int nf = 0; nf < NF; nf++) {
                int n = wn + nf * 8 + (lane >> 2);
                bfr[nf][0] = Bs[n * APu + kb];
                bfr[nf][1] = Bs[n * APu + kb + 4];
            }
#pragma unroll
            for (int mf = 0; mf < MF; mf++)
#pragma unroll
                for (int nf = 0; nf < NF; nf++)
                    mma_f16(acc[mf][nf], af[mf], bfr[nf]);
        }
    };

#pragma unroll
    for (int s = 0; s < S - 1; s++) {
        if (s < nch) load_stage(s, s);
        CP_COMMIT();
    }
    for (int kc = 0; kc < nch; kc++) {
        CP_WAIT(S - 2);
        __syncthreads();
        if (kc + S - 1 < nch) load_stage((kc + S - 1) % S, kc + S - 1);
        CP_COMMIT();
        compute_stage(kc % S);
        __syncthreads();
    }

#pragma unroll
    for (int mf = 0; mf < MF; mf++) {
#pragma unroll
        for (int nf = 0; nf < NF; nf++) {
            int row = wm + mf * 16 + (lane >> 2);
            int col = wn + nf * 8 + (lane & 3) * 2;
            float2 v0 = make_float2(rna_tf32(acc[mf][nf][0]),
                                    rna_tf32(acc[mf][nf][1]));
            float2 v1 = make_float2(rna_tf32(acc[mf][nf][2]),
                                    rna_tf32(acc[mf][nf][3]));
            *reinterpret_cast<float2*>(Cb + (long long)row * Ncols + col) = v0;
            *reinterpret_cast<float2*>(Cb + (long long)(row + 8) * Ncols + col) = v1;
        }
    }
}

// ---------------------------------------------------------------------------
// TF32 mma.sync GEMM + fused bias/LN/ReLU epilogues (BN == Ncols == 256).
// EPI_LN_TF16: writes H^T as fp16 into outT [b][256][2048].
// EPI_LN_COLSUM: accumulates column sums into colsum (no tensor store).
// ---------------------------------------------------------------------------
template <int EPI>
__global__ __launch_bounds__(256)
void tf32_ln_gemm(const float* __restrict__ A, const float* __restrict__ Bm,
                  int Kd,
                  const float* __restrict__ bias,
                  const float* __restrict__ gamma,
                  const float* __restrict__ beta,
                  float* __restrict__ colsum,
                  __half* __restrict__ outT) {
    constexpr int BM = 128, BK = 32, BN = 256, S = 2;
    constexpr int WROWS = 2, WCOLS = 4;
    constexpr int WM = BM / WROWS, WN = BN / WCOLS;
    constexpr int MF = WM / 16, NF = WN / 8;
    constexpr int AP = 36, BP = BN + 8;
    constexpr int AS_F = BM * AP, BS_F = BK * BP;
    constexpr int ST_F = AS_F + BS_F;
    constexpr int EP = 260;

    extern __shared__ float smem[];
    const uint32_t sbase = smem_u32(smem);

    const int tid = threadIdx.x, lane = tid & 31, wid = tid >> 5;
    const int wm = (wid / WCOLS) * WM, wn = (wid % WCOLS) * WN;

    const float* Ab = A + (long long)blockIdx.y * BM * Kd;

    float acc[MF][NF][4];
#pragma unroll
    for (int i = 0; i < MF; i++)
#pragma unroll
        for (int j = 0; j < NF; j++)
#pragma unroll
            for (int r = 0; r < 4; r++) acc[i][j][r] = 0.f;

    const int nch = Kd >> 5;

    auto load_stage = [&](int s, int kc) {
        const float* Ak = Ab + kc * BK;
#pragma unroll
        for (int i = 0; i < 4; i++) {
            int idx = tid + i * 256;
            int r = idx >> 3, c4 = idx & 7;
            cp16(sbase + (uint32_t)(s * ST_F + r * AP + c4 * 4) * 4u,
                 Ak + (long long)r * Kd + c4 * 4);
        }
        const float* Bk = Bm + (long long)(kc * BK) * BN;
#pragma unroll
        for (int i = 0; i < 8; i++) {
            int idx = tid + i * 256;
            int r = idx >> 6, c4 = idx & 63;
            cp16(sbase + (uint32_t)(s * ST_F + AS_F + r * BP + c4 * 4) * 4u,
                 Bk + (long long)r * BN + c4 * 4);
        }
    };

    auto compute_stage = [&](int s) {
        const uint32_t* As = reinterpret_cast<const uint32_t*>(smem + s * ST_F);
        const uint32_t* Bs = reinterpret_cast<const uint32_t*>(smem + s * ST_F + AS_F);
#pragma unroll
        for (int kk = 0; kk < 4; kk++) {
            const int k0 = kk * 8;
            uint32_t af[MF][4], bfr[NF][2];
#pragma unroll
            for (int mf = 0; mf < MF; mf++) {
                int m = wm + mf * 16 + (lane >> 2);
                int k = k0 + (lane & 3);
                af[mf][0] = As[m * AP + k];
                af[mf][1] = As[(m + 8) * AP + k];
                af[mf][2] = As[m * AP + k + 4];
                af[mf][3] = As[(m + 8) * AP + k + 4];
            }
#pragma unroll
            for (int nf = 0; nf < NF; nf++) {
                int n = wn + nf * 8 + (lane >> 2);
                int k = k0 + (lane & 3);
                bfr[nf][0] = Bs[k * BP + n];
                bfr[nf][1] = Bs[(k + 4) * BP + n];
            }
#pragma unroll
            for (int mf = 0; mf < MF; mf++)
#pragma unroll
                for (int nf = 0; nf < NF; nf++)
                    mma_tf32(acc[mf][nf], af[mf], bfr[nf]);
        }
    };

#pragma unroll
    for (int s = 0; s < S - 1; s++) {
        if (s < nch) load_stage(s, s);
        CP_COMMIT();
    }
    for (int kc = 0; kc < nch; kc++) {
        CP_WAIT(S - 2);
        __syncthreads();
        if (kc + S - 1 < nch) load_stage((kc + S - 1) % S, kc + S - 1);
        CP_COMMIT();
        compute_stage(kc % S);
        __syncthreads();
    }

    // ---- stash accumulators to smem tile [128][EP] ----
    __syncthreads();
#pragma unroll
    for (int mf = 0; mf < MF; mf++) {
#pragma unroll
        for (int nf = 0; nf < NF; nf++) {
            int row = wm + mf * 16 + (lane >> 2);
            int col = wn + nf * 8 + (lane & 3) * 2;
            smem[row * EP + col]     = acc[mf][nf][0];
            smem[row * EP + col + 1] = acc[mf][nf][1];
            smem[(row + 8) * EP + col]     = acc[mf][nf][2];
            smem[(row + 8) * EP + col + 1] = acc[mf][nf][3];
        }
    }
    __syncthreads();

    float rb[8], rg[8], rt[8];
#pragma unroll
    for (int j = 0; j < 8; j++) {
        rb[j] = __ldg(&bias[lane * 8 + j]);
        rg[j] = __ldg(&gamma[lane * 8 + j]);
        rt[j] = __ldg(&beta[lane * 8 + j]);
    }

    const float inv = 1.f / (float)HD_;
#pragma unroll 1
    for (int rr = 0; rr < 16; rr++) {
        const int r = wid * 16 + rr;
        float x[8];
        float4 v0 = *reinterpret_cast<float4*>(&smem[r * EP + lane * 8]);
        float4 v1 = *reinterpret_cast<float4*>(&smem[r * EP + lane * 8 + 4]);
        x[0] = v0.x; x[1] = v0.y; x[2] = v0.z; x[3] = v0.w;
        x[4] = v1.x; x[5] = v1.y; x[6] = v1.z; x[7] = v1.w;
        float s = 0.f, s2 = 0.f;
#pragma unroll
        for (int j = 0; j < 8; j++) {
            x[j] += rb[j];
            s += x[j]; s2 += x[j] * x[j];
        }
#pragma unroll
        for (int o = 16; o; o >>= 1) {
            s  += __shfl_xor_sync(0xFFFFFFFFu, s, o);
            s2 += __shfl_xor_sync(0xFFFFFFFFu, s2, o);
        }
        float mu = s * inv;
        float rstd = rsqrtf(s2 * inv - mu * mu + 1e-5f);
        float y[8];
#pragma unroll
        for (int j = 0; j < 8; j++) {
            float v = (x[j] - mu) * rstd * rg[j] + rt[j];
            y[j] = fmaxf(v, 0.f);
        }
        *reinterpret_cast<float4*>(&smem[r * EP + lane * 8]) =
            make_float4(y[0], y[1], y[2], y[3]);
        *reinterpret_cast<float4*>(&smem[r * EP + lane * 8 + 4]) =
            make_float4(y[4], y[5], y[6], y[7]);
    }
    __syncthreads();

    const int bb = (int)(blockIdx.y >> 4);       // batch (16 row-tiles each)

    if (EPI == EPI_LN_COLSUM) {
        float s = 0.f;
#pragma unroll 8
        for (int r = 0; r < BM; r++) s += smem[r * EP + tid];
        atomicAdd(&colsum[bb * HD_ + tid], s);
    } else {  // EPI_LN_TF16: thread owns column n=tid, write transposed fp16
        const int k0 = ((int)blockIdx.y & 15) * BM;
#pragma unroll 1
        for (int q = 0; q < 4; q++) {
            uint32_t pk[16];
#pragma unroll
            for (int r2 = 0; r2 < 16; r2++) {
                int r = q * 32 + 2 * r2;
                pk[r2] = pack_h2(smem[r * EP + tid], smem[(r + 1) * EP + tid]);
            }
            uint4* dst = reinterpret_cast<uint4*>(
                outT + ((long long)(bb * HD_ + tid) * N_ + k0 + q * 32));
#pragma unroll
            for (int j = 0; j < 4; j++)
                dst[j] = make_uint4(pk[4 * j], pk[4 * j + 1],
                                    pk[4 * j + 2], pk[4 * j + 3]);
        }
    }
}

// ---------------------------------------------------------------------------
__global__ __launch_bounds__(256)
void head_kernel(const float* __restrict__ colsum, const float* __restrict__ gvec,
                 const float* __restrict__ Ws, const float* __restrict__ bs,
                 const float* __restrict__ Wa, const float* __restrict__ ba,
                 float* __restrict__ out) {
    int b = blockIdx.x, t = threadIdx.x;
    __shared__ float fused[FUSE_];
    fused[t] = colsum[b * HD_ + t] * (1.f / (float)N_);
    if (t < G_) fused[HD_ + t] = gvec[b * G_ + t];
    __syncthreads();

    if (t < K_) {
        float acc = ba[t];
#pragma unroll 4
        for (int i = 0; i < FUSE_; i++) acc += fused[i] * Wa[i * K_ + t];
        out[B_ + b * K_ + t] = acc;
    } else if (t == K_) {
        float acc = bs[0];
        for (int i = 0; i < FUSE_; i++) acc += fused[i] * Ws[i];
        out[b] = acc;
    }
}

// ---------------------------------------------------------------------------
extern "C" void kernel_launch(void* const* d_in, const int* in_sizes, int n_in,
                              void* d_out, int out_size) {
    const float* A_hat = (const float*)d_in[0];
    const float* X     = (const float*)d_in[1];
    const float* gvec  = (const float*)d_in[2];
    const float* W1    = (const float*)d_in[3];
    const float* b1    = (const float*)d_in[4];
    const float* g1    = (const float*)d_in[5];
    const float* be1   = (const float*)d_in[6];
    const float* W2    = (const float*)d_in[7];
    const float* b2    = (const float*)d_in[8];
    const float* g2    = (const float*)d_in[9];
    const float* be2   = (const float*)d_in[10];
    const float* Ws    = (const float*)d_in[11];
    const float* bs    = (const float*)d_in[12];
    const float* Wa    = (const float*)d_in[13];
    const float* ba    = (const float*)d_in[14];
    float* out = (float*)d_out;

    float *buf1, *buf2, *csum, *bW1, *bW2;
    __half *Ah, *XT, *H1T;
    cudaGetSymbolAddress((void**)&buf1, g_buf1);
    cudaGetSymbolAddress((void**)&buf2, g_buf2);
    cudaGetSymbolAddress((void**)&csum, g_colsum);
    cudaGetSymbolAddress((void**)&Ah,  g_Ah);
    cudaGetSymbolAddress((void**)&XT,  g_XT);
    cudaGetSymbolAddress((void**)&H1T, g_H1T);
    cudaGetSymbolAddress((void**)&bW1, g_bufW1);
    cudaGetSymbolAddress((void**)&bW2, g_bufW2);

    constexpr int SMEM_K1 = (2 * 128 * 20 + 3 * 64 * 20) * 4;  // 35840
    constexpr int SMEM_K3 = 4 * ((128 + 128) * 20) * 4;        // 81920
    constexpr int SMEM_LN = 128 * 260 * 4;                     // 133120

    auto k1 = k1_conv_gemm<2>;
    auto k3 = f16_mma_gemm<128, 2, 4, 4, 2>;
    auto k2 = tf32_ln_gemm<EPI_LN_TF16>;
    auto k4 = tf32_ln_gemm<EPI_LN_COLSUM>;

    cudaFuncSetAttribute((const void*)k1, cudaFuncAttributeMaxDynamicSharedMemorySize, SMEM_K1);
    cudaFuncSetAttribute((const void*)k3, cudaFuncAttributeMaxDynamicSharedMemorySize, SMEM_K3);
    cudaFuncSetAttribute((const void*)k2, cudaFuncAttributeMaxDynamicSharedMemorySize, SMEM_LN);
    cudaFuncSetAttribute((const void*)k4, cudaFuncAttributeMaxDynamicSharedMemorySize, SMEM_LN);

    // Prep: X -> XT fp16, W -> tf32, csum = 0
    transpose_x_kernel<<<dim3(F_ / 32, N_ / 32, B_), 256>>>(X, XT);
    round_tf32_kernel<<<(F_ * HD_ / 4 + 255) / 256, 256>>>(W1, bW1, F_ * HD_ / 4);
    round_tf32_kernel<<<(HD_ * HD_ / 4 + 255) / 256, 256>>>(W2, bW2, HD_ * HD_ / 4);
    cudaMemsetAsync(csum, 0, B_ * HD_ * sizeof(float));

    // K1 (fused): T1 = fp16(A_hat) @ XT^T -> buf1; also writes Ah fp16
    k1<<<dim3(1, 16, 16), 256, SMEM_K1>>>(A_hat, XT, buf1, Ah);
    // K2: H1T = fp16_T(relu(LN(T1 @ W1 + b1)))  (tf32, flat 32768x64 @ 64x256)
    k2<<<dim3(1, 256, 1), 256, SMEM_LN>>>(
        buf1, bW1, F_, b1, g1, be1, nullptr, H1T);
    // K3: T2 = Ah @ H1T^T  (fp16, per batch 2048x2048 @ 2048x256) -> buf2
    k3<<<dim3(2, 16, 16), 256, SMEM_K3>>>(
        Ah, H1T, buf2, N_, HD_,
        (long long)N_ * N_, (long long)HD_ * N_, (long long)N_ * HD_);
    // K4: colsum += colsums(relu(LN(T2 @ W2 + b2)))  (tf32)
    k4<<<dim3(1, 256, 1), 256, SMEM_LN>>>(
        buf2, bW2, HD_, b2, g2, be2, csum, nullptr);
    // K5: mean + concat + heads -> out
    head_kernel<<<B_, 256>>>(csum, gvec, Ws, bs, Wa, ba, out);
}